// round 2
// baseline (speedup 1.0000x reference)
#include <cuda_runtime.h>
#include <math.h>

// Problem-shape constants (from reference setup_inputs)
#define NMAX 50000
#define EMAX 800000
#define ETMAX (EMAX + NMAX)

// ---------------- device scratch (no allocations allowed) ----------------
__device__ __align__(16) float g_h1[NMAX * 256];    // x @ W1            [N,256]
__device__ __align__(16) float g_out1[NMAX * 256];  // layer1 aggregate  [N,256]
__device__ __align__(16) float g_h2[NMAX * 128];    // out1 @ W2         [N,128]
__device__ __align__(16) float g_es1[NMAX * 4];
__device__ __align__(16) float g_ed1[NMAX * 4];
__device__ __align__(16) float g_z1[NMAX * 4];
__device__ __align__(16) float g_p1[(size_t)ETMAX * 4];
__device__ __align__(16) float g_es2[NMAX];
__device__ __align__(16) float g_ed2[NMAX];
__device__ __align__(16) float g_z2[NMAX];
__device__ __align__(16) float g_p2[ETMAX];

// sm_90+ vectorized global reduction: 1 instruction for 4 float adds
__device__ __forceinline__ void red_add_v4(float* addr, float4 v) {
    asm volatile("red.global.add.v4.f32 [%0], {%1,%2,%3,%4};"
                 :: "l"(addr), "f"(v.x), "f"(v.y), "f"(v.z), "f"(v.w)
                 : "memory");
}

// ---------------- SGEMM: C[M,N] = A[M,K] @ B[K,N] (row-major) ----------------
// 128x128 block, BK=8, 8x8 per thread, 256 threads. N % 128 == 0, K % 8 == 0.
__device__ __forceinline__ void sgemm_body(int M, int N, int K,
                                           const float* __restrict__ A,
                                           const float* __restrict__ B,
                                           float* __restrict__ C) {
    __shared__ float As[8][128];
    __shared__ float Bs[8][128];
    const int tid  = threadIdx.x;
    const int brow = blockIdx.y * 128;
    const int bcol = blockIdx.x * 128;
    const int trow = (tid >> 4) * 8;
    const int tcol = (tid & 15) * 8;
    const int arow = tid >> 1;
    const int acol = (tid & 1) << 2;
    const int blrow = tid >> 5;
    const int blcol = (tid & 31) << 2;

    float acc[8][8] = {};

    for (int k0 = 0; k0 < K; k0 += 8) {
        float4 av = make_float4(0.f, 0.f, 0.f, 0.f);
        if (brow + arow < M)
            av = *(const float4*)&A[(size_t)(brow + arow) * K + k0 + acol];
        As[acol + 0][arow] = av.x;
        As[acol + 1][arow] = av.y;
        As[acol + 2][arow] = av.z;
        As[acol + 3][arow] = av.w;
        *(float4*)&Bs[blrow][blcol] =
            *(const float4*)&B[(size_t)(k0 + blrow) * N + bcol + blcol];
        __syncthreads();
#pragma unroll
        for (int k = 0; k < 8; k++) {
            float4 a0 = *(const float4*)&As[k][trow];
            float4 a1 = *(const float4*)&As[k][trow + 4];
            float4 b0 = *(const float4*)&Bs[k][tcol];
            float4 b1 = *(const float4*)&Bs[k][tcol + 4];
            float ra[8] = {a0.x, a0.y, a0.z, a0.w, a1.x, a1.y, a1.z, a1.w};
            float rb[8] = {b0.x, b0.y, b0.z, b0.w, b1.x, b1.y, b1.z, b1.w};
#pragma unroll
            for (int i = 0; i < 8; i++)
#pragma unroll
                for (int j = 0; j < 8; j++)
                    acc[i][j] = fmaf(ra[i], rb[j], acc[i][j]);
        }
        __syncthreads();
    }
#pragma unroll
    for (int i = 0; i < 8; i++) {
        int grow = brow + trow + i;
        if (grow < M) {
            *(float4*)&C[(size_t)grow * N + bcol + tcol] =
                make_float4(acc[i][0], acc[i][1], acc[i][2], acc[i][3]);
            *(float4*)&C[(size_t)grow * N + bcol + tcol + 4] =
                make_float4(acc[i][4], acc[i][5], acc[i][6], acc[i][7]);
        }
    }
}

__global__ __launch_bounds__(256) void gemm1_k(const float* __restrict__ x,
                                               const float* __restrict__ W1, int M) {
    sgemm_body(M, 256, 128, x, W1, g_h1);
}
__global__ __launch_bounds__(256) void gemm2_k(const float* __restrict__ W2, int M) {
    sgemm_body(M, 128, 256, g_out1, W2, g_h2);
}

// ---------------- attention scores (warp per node) ----------------
__global__ void scores1_k(const float* __restrict__ as1,
                          const float* __restrict__ ad1, int N) {
    int gw = (blockIdx.x * blockDim.x + threadIdx.x) >> 5;
    int lane = threadIdx.x & 31;
    if (gw >= N) return;
    const float* row = g_h1 + (size_t)gw * 256;
#pragma unroll
    for (int h = 0; h < 4; h++) {
        float v0 = row[h * 64 + lane], v1 = row[h * 64 + lane + 32];
        float s = v0 * as1[h * 64 + lane] + v1 * as1[h * 64 + lane + 32];
        float d = v0 * ad1[h * 64 + lane] + v1 * ad1[h * 64 + lane + 32];
#pragma unroll
        for (int o = 16; o; o >>= 1) {
            s += __shfl_xor_sync(0xffffffffu, s, o);
            d += __shfl_xor_sync(0xffffffffu, d, o);
        }
        if (lane == 0) { g_es1[gw * 4 + h] = s; g_ed1[gw * 4 + h] = d; }
    }
}

__global__ void scores2_k(const float* __restrict__ as2,
                          const float* __restrict__ ad2, int N) {
    int gw = (blockIdx.x * blockDim.x + threadIdx.x) >> 5;
    int lane = threadIdx.x & 31;
    if (gw >= N) return;
    const float* row = g_h2 + (size_t)gw * 128;
    float s = 0.f, d = 0.f;
#pragma unroll
    for (int c = lane; c < 128; c += 32) {
        float v = row[c];
        s += v * as2[c];
        d += v * ad2[c];
    }
#pragma unroll
    for (int o = 16; o; o >>= 1) {
        s += __shfl_xor_sync(0xffffffffu, s, o);
        d += __shfl_xor_sync(0xffffffffu, d, o);
    }
    if (lane == 0) { g_es2[gw] = s; g_ed2[gw] = d; }
}

// ---------------- zero init ----------------
__global__ void zero1_k(int N) {
    int i = blockIdx.x * blockDim.x + threadIdx.x;
    if (i < N * 256) g_out1[i] = 0.f;
    if (i < N * 4) g_z1[i] = 0.f;
}
__global__ void zero2_k(float* __restrict__ out, int N) {
    int i = blockIdx.x * blockDim.x + threadIdx.x;
    if (i < N * 128) out[i] = 0.f;
    if (i < N) g_z2[i] = 0.f;
}

// ---------------- edge softmax numerators + denominators ----------------
// No max-shift needed: scores are O(1) scale (fan-in-scaled weights), exp is safe
// in fp32, and alpha = p/z is identical to the max-shifted version.
__global__ void edgep1_k(const int* __restrict__ ei, int E, int Et) {
    int e = blockIdx.x * blockDim.x + threadIdx.x;
    if (e >= Et) return;
    int s, d;
    if (e < E) { s = ei[e]; d = ei[E + e]; } else { s = e - E; d = s; }
    float4 a = *(const float4*)&g_es1[s * 4];
    float4 b = *(const float4*)&g_ed1[d * 4];
    float4 p; float t;
    t = a.x + b.x; t = t > 0.f ? t : 0.2f * t; p.x = expf(t);
    t = a.y + b.y; t = t > 0.f ? t : 0.2f * t; p.y = expf(t);
    t = a.z + b.z; t = t > 0.f ? t : 0.2f * t; p.z = expf(t);
    t = a.w + b.w; t = t > 0.f ? t : 0.2f * t; p.w = expf(t);
    *(float4*)&g_p1[(size_t)e * 4] = p;
    red_add_v4(&g_z1[d * 4], p);
}

__global__ void edgep2_k(const int* __restrict__ ei, int E, int Et) {
    int e = blockIdx.x * blockDim.x + threadIdx.x;
    if (e >= Et) return;
    int s, d;
    if (e < E) { s = ei[e]; d = ei[E + e]; } else { s = e - E; d = s; }
    float t = g_es2[s] + g_ed2[d];
    t = t > 0.f ? t : 0.2f * t;
    float p = expf(t);
    g_p2[e] = p;
    atomicAdd(&g_z2[d], p);
}

// ---------------- edge aggregation (scatter with vector atomics) ----------------
// layer1: 64 float4-lanes per edge (256 feats), layer2: 32 lanes (128 feats)
__global__ void agg1_k(const int* __restrict__ ei, int E, int Et) {
    long long tid = (long long)blockIdx.x * blockDim.x + threadIdx.x;
    int e = (int)(tid >> 6);
    if (e >= Et) return;
    int q = (int)tid & 63;
    int s, d;
    if (e < E) { s = ei[e]; d = ei[E + e]; } else { s = e - E; d = s; }
    int h = q >> 4;
    float alpha = g_p1[(size_t)e * 4 + h] / g_z1[d * 4 + h];
    float4 v = *(const float4*)&g_h1[(size_t)s * 256 + q * 4];
    v.x *= alpha; v.y *= alpha; v.z *= alpha; v.w *= alpha;
    red_add_v4(&g_out1[(size_t)d * 256 + q * 4], v);
}

__global__ void agg2_k(const int* __restrict__ ei, int E, int Et,
                       float* __restrict__ out) {
    long long tid = (long long)blockIdx.x * blockDim.x + threadIdx.x;
    int e = (int)(tid >> 5);
    if (e >= Et) return;
    int q = (int)tid & 31;
    int s, d;
    if (e < E) { s = ei[e]; d = ei[E + e]; } else { s = e - E; d = s; }
    float alpha = g_p2[e] / g_z2[d];
    float4 v = *(const float4*)&g_h2[(size_t)s * 128 + q * 4];
    v.x *= alpha; v.y *= alpha; v.z *= alpha; v.w *= alpha;
    red_add_v4(&out[(size_t)d * 128 + q * 4], v);
}

// ---------------- epilogues ----------------
__global__ void elu1_k(const float* __restrict__ b1, int N) {
    int i = blockIdx.x * blockDim.x + threadIdx.x;
    if (i >= N * 256) return;
    float v = g_out1[i] + b1[i & 255];
    g_out1[i] = v > 0.f ? v : expm1f(v);
}
__global__ void bias2_k(float* __restrict__ out, const float* __restrict__ b2, int N) {
    int i = blockIdx.x * blockDim.x + threadIdx.x;
    if (i < N * 128) out[i] += b2[i & 127];
}

// ---------------- launch ----------------
extern "C" void kernel_launch(void* const* d_in, const int* in_sizes, int n_in,
                              void* d_out, int out_size) {
    const float* x   = (const float*)d_in[0];
    const int*   ei  = (const int*)d_in[1];
    const float* W1  = (const float*)d_in[2];
    const float* as1 = (const float*)d_in[3];
    const float* ad1 = (const float*)d_in[4];
    const float* b1  = (const float*)d_in[5];
    const float* W2  = (const float*)d_in[6];
    const float* as2 = (const float*)d_in[7];
    const float* ad2 = (const float*)d_in[8];
    const float* b2  = (const float*)d_in[9];
    float* out = (float*)d_out;

    int N  = in_sizes[0] / 128;  // in_dim = 128
    int E  = in_sizes[1] / 2;
    int Et = E + N;

    // ---- Layer 1 ----
    gemm1_k<<<dim3(2, (N + 127) / 128), 256>>>(x, W1, N);
    scores1_k<<<(N * 32 + 255) / 256, 256>>>(as1, ad1, N);
    zero1_k<<<(N * 256 + 255) / 256, 256>>>(N);
    edgep1_k<<<(Et + 255) / 256, 256>>>(ei, E, Et);
    agg1_k<<<(int)(((long long)Et * 64 + 255) / 256), 256>>>(ei, E, Et);
    elu1_k<<<(N * 256 + 255) / 256, 256>>>(b1, N);

    // ---- Layer 2 ----
    gemm2_k<<<dim3(1, (N + 127) / 128), 256>>>(W2, N);
    scores2_k<<<(N * 32 + 255) / 256, 256>>>(as2, ad2, N);
    zero2_k<<<(N * 128 + 255) / 256, 256>>>(out, N);
    edgep2_k<<<(Et + 255) / 256, 256>>>(ei, E, Et);
    agg2_k<<<(int)(((long long)Et * 32 + 255) / 256), 256>>>(ei, E, Et, out);
    bias2_k<<<(N * 128 + 255) / 256, 256>>>(out, b2, N);
}

// round 3
// speedup vs baseline: 1.8002x; 1.8002x over previous
#include <cuda_runtime.h>
#include <math.h>

// Problem-shape constants (from reference setup_inputs)
#define NMAX 50000
#define EMAX 800000
#define ETMAX (EMAX + NMAX)

// ---------------- device scratch (no allocations allowed) ----------------
__device__ __align__(16) float g_h1[NMAX * 256];    // x @ W1            [N,256]
__device__ __align__(16) float g_out1[NMAX * 256];  // layer1 out (post-ELU)
__device__ __align__(16) float g_h2[NMAX * 128];    // out1 @ W2         [N,128]
__device__ __align__(16) float g_es1[NMAX * 4];
__device__ __align__(16) float g_ed1[NMAX * 4];
__device__ __align__(16) float g_es2[NMAX];
__device__ __align__(16) float g_ed2[NMAX];

// CSR-by-destination (built once per launch, reused by both layers)
__device__ int g_cnt[NMAX];
__device__ int g_scan[NMAX];
__device__ int g_bsum[64];
__device__ int g_rp[NMAX + 1];
__device__ int g_cur[NMAX];
__device__ int g_csr[ETMAX];

// ---------------- SGEMM: C[M,N] = A[M,K] @ B[K,N] (row-major) ----------------
// 128x128 block, BK=8, 8x8 per thread, 256 threads. N % 128 == 0, K % 8 == 0.
__device__ __forceinline__ void sgemm_body(int M, int N, int K,
                                           const float* __restrict__ A,
                                           const float* __restrict__ B,
                                           float* __restrict__ C) {
    __shared__ float As[8][128];
    __shared__ float Bs[8][128];
    const int tid  = threadIdx.x;
    const int brow = blockIdx.y * 128;
    const int bcol = blockIdx.x * 128;
    const int trow = (tid >> 4) * 8;
    const int tcol = (tid & 15) * 8;
    const int arow = tid >> 1;
    const int acol = (tid & 1) << 2;
    const int blrow = tid >> 5;
    const int blcol = (tid & 31) << 2;

    float acc[8][8] = {};

    for (int k0 = 0; k0 < K; k0 += 8) {
        float4 av = make_float4(0.f, 0.f, 0.f, 0.f);
        if (brow + arow < M)
            av = *(const float4*)&A[(size_t)(brow + arow) * K + k0 + acol];
        As[acol + 0][arow] = av.x;
        As[acol + 1][arow] = av.y;
        As[acol + 2][arow] = av.z;
        As[acol + 3][arow] = av.w;
        *(float4*)&Bs[blrow][blcol] =
            *(const float4*)&B[(size_t)(k0 + blrow) * N + bcol + blcol];
        __syncthreads();
#pragma unroll
        for (int k = 0; k < 8; k++) {
            float4 a0 = *(const float4*)&As[k][trow];
            float4 a1 = *(const float4*)&As[k][trow + 4];
            float4 b0 = *(const float4*)&Bs[k][tcol];
            float4 b1 = *(const float4*)&Bs[k][tcol + 4];
            float ra[8] = {a0.x, a0.y, a0.z, a0.w, a1.x, a1.y, a1.z, a1.w};
            float rb[8] = {b0.x, b0.y, b0.z, b0.w, b1.x, b1.y, b1.z, b1.w};
#pragma unroll
            for (int i = 0; i < 8; i++)
#pragma unroll
                for (int j = 0; j < 8; j++)
                    acc[i][j] = fmaf(ra[i], rb[j], acc[i][j]);
        }
        __syncthreads();
    }
#pragma unroll
    for (int i = 0; i < 8; i++) {
        int grow = brow + trow + i;
        if (grow < M) {
            *(float4*)&C[(size_t)grow * N + bcol + tcol] =
                make_float4(acc[i][0], acc[i][1], acc[i][2], acc[i][3]);
            *(float4*)&C[(size_t)grow * N + bcol + tcol + 4] =
                make_float4(acc[i][4], acc[i][5], acc[i][6], acc[i][7]);
        }
    }
}

__global__ __launch_bounds__(256) void gemm1_k(const float* __restrict__ x,
                                               const float* __restrict__ W1, int M) {
    sgemm_body(M, 256, 128, x, W1, g_h1);
}
__global__ __launch_bounds__(256) void gemm2_k(const float* __restrict__ W2, int M) {
    sgemm_body(M, 128, 256, g_out1, W2, g_h2);
}

// ---------------- CSR build ----------------
__global__ void zeroc_k(int N) {
    int i = blockIdx.x * blockDim.x + threadIdx.x;
    if (i < N) g_cnt[i] = 0;
}
__global__ void count_k(const int* __restrict__ ei, int E, int Et) {
    int e = blockIdx.x * blockDim.x + threadIdx.x;
    if (e >= Et) return;
    int d = (e < E) ? ei[E + e] : (e - E);
    atomicAdd(&g_cnt[d], 1);
}
__global__ __launch_bounds__(1024) void scan1_k(int N) {
    __shared__ int sh[1024];
    int i = blockIdx.x * 1024 + threadIdx.x;
    int v = (i < N) ? g_cnt[i] : 0;
    sh[threadIdx.x] = v;
    __syncthreads();
#pragma unroll
    for (int off = 1; off < 1024; off <<= 1) {
        int t = (threadIdx.x >= off) ? sh[threadIdx.x - off] : 0;
        __syncthreads();
        sh[threadIdx.x] += t;
        __syncthreads();
    }
    if (i < N) g_scan[i] = sh[threadIdx.x];
    if (threadIdx.x == 1023) g_bsum[blockIdx.x] = sh[1023];
}
__global__ void scan2_k(int nb) {
    __shared__ int sh[64];
    int v = (threadIdx.x < nb) ? g_bsum[threadIdx.x] : 0;
    sh[threadIdx.x] = v;
    __syncthreads();
#pragma unroll
    for (int off = 1; off < 64; off <<= 1) {
        int t = (threadIdx.x >= off) ? sh[threadIdx.x - off] : 0;
        __syncthreads();
        sh[threadIdx.x] += t;
        __syncthreads();
    }
    if (threadIdx.x < nb)
        g_bsum[threadIdx.x] = threadIdx.x ? sh[threadIdx.x - 1] : 0;
}
__global__ void scan3_k(int N, int Et) {
    int i = blockIdx.x * blockDim.x + threadIdx.x;
    if (i >= N) return;
    int excl = g_scan[i] - g_cnt[i] + g_bsum[i >> 10];
    g_rp[i] = excl;
    g_cur[i] = excl;
    if (i == 0) g_rp[N] = Et;
}
__global__ void fill_k(const int* __restrict__ ei, int E, int Et) {
    int e = blockIdx.x * blockDim.x + threadIdx.x;
    if (e >= Et) return;
    int s, d;
    if (e < E) { s = ei[e]; d = ei[E + e]; } else { s = e - E; d = s; }
    int pos = atomicAdd(&g_cur[d], 1);
    g_csr[pos] = s;
}

// ---------------- attention scores (warp per node) ----------------
__global__ void scores1_k(const float* __restrict__ as1,
                          const float* __restrict__ ad1, int N) {
    int gw = (blockIdx.x * blockDim.x + threadIdx.x) >> 5;
    int lane = threadIdx.x & 31;
    if (gw >= N) return;
    const float* row = g_h1 + (size_t)gw * 256;
#pragma unroll
    for (int h = 0; h < 4; h++) {
        float v0 = row[h * 64 + lane], v1 = row[h * 64 + lane + 32];
        float s = v0 * as1[h * 64 + lane] + v1 * as1[h * 64 + lane + 32];
        float d = v0 * ad1[h * 64 + lane] + v1 * ad1[h * 64 + lane + 32];
#pragma unroll
        for (int o = 16; o; o >>= 1) {
            s += __shfl_xor_sync(0xffffffffu, s, o);
            d += __shfl_xor_sync(0xffffffffu, d, o);
        }
        if (lane == 0) { g_es1[gw * 4 + h] = s; g_ed1[gw * 4 + h] = d; }
    }
}

__global__ void scores2_k(const float* __restrict__ as2,
                          const float* __restrict__ ad2, int N) {
    int gw = (blockIdx.x * blockDim.x + threadIdx.x) >> 5;
    int lane = threadIdx.x & 31;
    if (gw >= N) return;
    const float* row = g_h2 + (size_t)gw * 128;
    float s = 0.f, d = 0.f;
#pragma unroll
    for (int c = lane; c < 128; c += 32) {
        float v = row[c];
        s += v * as2[c];
        d += v * ad2[c];
    }
#pragma unroll
    for (int o = 16; o; o >>= 1) {
        s += __shfl_xor_sync(0xffffffffu, s, o);
        d += __shfl_xor_sync(0xffffffffu, d, o);
    }
    if (lane == 0) { g_es2[gw] = s; g_ed2[gw] = d; }
}

// ---------------- fused gather aggregation (warp per destination node) ----------
// out1[d] = elu( (sum_e p_e * h1[src_e]) / (sum_e p_e) + b1 )
__device__ __forceinline__ void agg1_edge(int s, float4 ed, int lane, int h,
                                          float4& a0, float4& a1, float4& z) {
    float4 es = *(const float4*)&g_es1[s * 4];
    float t;
    float4 p;
    t = es.x + ed.x; t = t > 0.f ? t : 0.2f * t; p.x = __expf(t);
    t = es.y + ed.y; t = t > 0.f ? t : 0.2f * t; p.y = __expf(t);
    t = es.z + ed.z; t = t > 0.f ? t : 0.2f * t; p.z = __expf(t);
    t = es.w + ed.w; t = t > 0.f ? t : 0.2f * t; p.w = __expf(t);
    z.x += p.x; z.y += p.y; z.z += p.z; z.w += p.w;
    float ph = h == 0 ? p.x : (h == 1 ? p.y : (h == 2 ? p.z : p.w));
    const float4* row = (const float4*)&g_h1[(size_t)s * 256];
    float4 v0 = row[lane * 2], v1 = row[lane * 2 + 1];
    a0.x = fmaf(ph, v0.x, a0.x); a0.y = fmaf(ph, v0.y, a0.y);
    a0.z = fmaf(ph, v0.z, a0.z); a0.w = fmaf(ph, v0.w, a0.w);
    a1.x = fmaf(ph, v1.x, a1.x); a1.y = fmaf(ph, v1.y, a1.y);
    a1.z = fmaf(ph, v1.z, a1.z); a1.w = fmaf(ph, v1.w, a1.w);
}

__global__ __launch_bounds__(256) void agg1_k(const float* __restrict__ b1, int N) {
    int d = (blockIdx.x * blockDim.x + threadIdx.x) >> 5;
    int lane = threadIdx.x & 31;
    if (d >= N) return;
    float4 ed = *(const float4*)&g_ed1[d * 4];
    int beg = g_rp[d], end = g_rp[d + 1];
    int h = lane >> 3;  // lane covers cols [lane*8, lane*8+8) ; head = col/64
    float4 a0 = {0, 0, 0, 0}, a1 = {0, 0, 0, 0}, z = {0, 0, 0, 0};
    int i = beg;
    for (; i + 1 < end; i += 2) {
        int s0 = g_csr[i], s1 = g_csr[i + 1];
        agg1_edge(s0, ed, lane, h, a0, a1, z);
        agg1_edge(s1, ed, lane, h, a0, a1, z);
    }
    if (i < end) agg1_edge(g_csr[i], ed, lane, h, a0, a1, z);

    float zh = h == 0 ? z.x : (h == 1 ? z.y : (h == 2 ? z.z : z.w));
    float inv = 1.f / zh;
    int col = lane * 8;
    float4 bb0 = *(const float4*)&b1[col];
    float4 bb1 = *(const float4*)&b1[col + 4];
    float4 o0, o1;
    float v;
    v = a0.x * inv + bb0.x; o0.x = v > 0.f ? v : expm1f(v);
    v = a0.y * inv + bb0.y; o0.y = v > 0.f ? v : expm1f(v);
    v = a0.z * inv + bb0.z; o0.z = v > 0.f ? v : expm1f(v);
    v = a0.w * inv + bb0.w; o0.w = v > 0.f ? v : expm1f(v);
    v = a1.x * inv + bb1.x; o1.x = v > 0.f ? v : expm1f(v);
    v = a1.y * inv + bb1.y; o1.y = v > 0.f ? v : expm1f(v);
    v = a1.z * inv + bb1.z; o1.z = v > 0.f ? v : expm1f(v);
    v = a1.w * inv + bb1.w; o1.w = v > 0.f ? v : expm1f(v);
    float* outr = &g_out1[(size_t)d * 256 + col];
    *(float4*)outr = o0;
    *(float4*)(outr + 4) = o1;
}

// out[d] = (sum_e p_e * h2[src_e]) / (sum_e p_e) + b2
__global__ __launch_bounds__(256) void agg2_k(float* __restrict__ out,
                                              const float* __restrict__ b2, int N) {
    int d = (blockIdx.x * blockDim.x + threadIdx.x) >> 5;
    int lane = threadIdx.x & 31;
    if (d >= N) return;
    float edv = g_ed2[d];
    int beg = g_rp[d], end = g_rp[d + 1];
    float4 acc = {0, 0, 0, 0};
    float z = 0.f;
    int i = beg;
    for (; i < end; i++) {
        int s = g_csr[i];
        float t = g_es2[s] + edv;
        t = t > 0.f ? t : 0.2f * t;
        float p = __expf(t);
        z += p;
        float4 vv = *(const float4*)&g_h2[(size_t)s * 128 + lane * 4];
        acc.x = fmaf(p, vv.x, acc.x); acc.y = fmaf(p, vv.y, acc.y);
        acc.z = fmaf(p, vv.z, acc.z); acc.w = fmaf(p, vv.w, acc.w);
    }
    float inv = 1.f / z;
    int col = lane * 4;
    float4 bb = *(const float4*)&b2[col];
    float4 o;
    o.x = acc.x * inv + bb.x; o.y = acc.y * inv + bb.y;
    o.z = acc.z * inv + bb.z; o.w = acc.w * inv + bb.w;
    *(float4*)&out[(size_t)d * 128 + col] = o;
}

// ---------------- launch ----------------
extern "C" void kernel_launch(void* const* d_in, const int* in_sizes, int n_in,
                              void* d_out, int out_size) {
    const float* x   = (const float*)d_in[0];
    const int*   ei  = (const int*)d_in[1];
    const float* W1  = (const float*)d_in[2];
    const float* as1 = (const float*)d_in[3];
    const float* ad1 = (const float*)d_in[4];
    const float* b1  = (const float*)d_in[5];
    const float* W2  = (const float*)d_in[6];
    const float* as2 = (const float*)d_in[7];
    const float* ad2 = (const float*)d_in[8];
    const float* b2  = (const float*)d_in[9];
    float* out = (float*)d_out;

    int N  = in_sizes[0] / 128;  // in_dim = 128
    int E  = in_sizes[1] / 2;
    int Et = E + N;
    int nb = (N + 1023) / 1024;

    // ---- CSR build (dst-sorted edge index, shared by both layers) ----
    zeroc_k<<<(N + 255) / 256, 256>>>(N);
    count_k<<<(Et + 255) / 256, 256>>>(ei, E, Et);
    scan1_k<<<nb, 1024>>>(N);
    scan2_k<<<1, 64>>>(nb);
    scan3_k<<<(N + 255) / 256, 256>>>(N, Et);
    fill_k<<<(Et + 255) / 256, 256>>>(ei, E, Et);

    // ---- Layer 1 ----
    gemm1_k<<<dim3(2, (N + 127) / 128), 256>>>(x, W1, N);
    scores1_k<<<(N * 32 + 255) / 256, 256>>>(as1, ad1, N);
    agg1_k<<<(N * 32 + 255) / 256, 256>>>(b1, N);

    // ---- Layer 2 ----
    gemm2_k<<<dim3(1, (N + 127) / 128), 256>>>(W2, N);
    scores2_k<<<(N * 32 + 255) / 256, 256>>>(as2, ad2, N);
    agg2_k<<<(N * 32 + 255) / 256, 256>>>(out, b2, N);
}

// round 9
// speedup vs baseline: 2.1133x; 1.1739x over previous
#include <cuda_runtime.h>
#include <cuda_fp16.h>
#include <cstdint>
#include <math.h>

// Problem-shape constants (from reference setup_inputs)
#define NMAX 50000
#define EMAX 800000
#define ETMAX (EMAX + NMAX)

// ---------------- device scratch (no allocations allowed) ----------------
__device__ __align__(16) __half g_h1h[NMAX * 256];  // x@W1 as fp16 (gather src)
__device__ __align__(16) float g_out1[NMAX * 256];  // layer1 out (post-ELU)
__device__ __align__(16) float g_h2[NMAX * 128];    // out1 @ W2
__device__ __align__(16) float g_es1[NMAX * 4];
__device__ __align__(16) float g_ed1[NMAX * 4];
__device__ __align__(16) float g_es2[NMAX];
__device__ __align__(16) float g_ed2[NMAX];

// CSR-by-destination (built once per launch, reused by both layers)
__device__ int g_cnt[NMAX];
__device__ int g_scan[NMAX];
__device__ int g_bsum[64];
__device__ int g_rp[NMAX + 1];
__device__ int g_cur[NMAX];
__device__ int g_csr[ETMAX];

// ---------------- fused SGEMM + attention-score epilogue ----------------
// C[M,NN] = A[M,KK] @ B[KK,NN]; 128x128 tile, BK=8, 8x8/thread, 256 threads.
// Epilogue: es[row,h] = sum_c C[row, h*Ch + c] * a_src[h*Ch + c] (ed likewise),
// computed from exact fp32 accumulators. Optionally stores C as fp16.
template <int NN, int KK, int HEADS, bool F16OUT>
__device__ __forceinline__ void gemm_fused_body(
    int M, const float* __restrict__ A, const float* __restrict__ B,
    float* __restrict__ Cf, __half* __restrict__ Ch,
    const float* __restrict__ va_s, const float* __restrict__ va_d,
    float* __restrict__ es, float* __restrict__ ed) {
    __shared__ float As[8][128];
    __shared__ float Bs[8][128];
    const int tid  = threadIdx.x;
    const int brow = blockIdx.y * 128;
    const int bcol = blockIdx.x * 128;
    const int trow = (tid >> 4) * 8;
    const int tcol = (tid & 15) * 8;
    const int arow = tid >> 1;
    const int acol = (tid & 1) << 2;
    const int blrow = tid >> 5;
    const int blcol = (tid & 31) << 2;

    float acc[8][8] = {};

    // software-pipelined prefetch
    float4 av = make_float4(0.f, 0.f, 0.f, 0.f);
    if (brow + arow < M)
        av = *(const float4*)&A[(size_t)(brow + arow) * KK + acol];
    float4 bv = *(const float4*)&B[(size_t)blrow * NN + bcol + blcol];

    for (int k0 = 0; k0 < KK; k0 += 8) {
        As[acol + 0][arow] = av.x;
        As[acol + 1][arow] = av.y;
        As[acol + 2][arow] = av.z;
        As[acol + 3][arow] = av.w;
        *(float4*)&Bs[blrow][blcol] = bv;
        __syncthreads();
        if (k0 + 8 < KK) {
            av = make_float4(0.f, 0.f, 0.f, 0.f);
            if (brow + arow < M)
                av = *(const float4*)&A[(size_t)(brow + arow) * KK + k0 + 8 + acol];
            bv = *(const float4*)&B[(size_t)(k0 + 8 + blrow) * NN + bcol + blcol];
        }
#pragma unroll
        for (int k = 0; k < 8; k++) {
            float4 a0 = *(const float4*)&As[k][trow];
            float4 a1 = *(const float4*)&As[k][trow + 4];
            float4 b0 = *(const float4*)&Bs[k][tcol];
            float4 b1 = *(const float4*)&Bs[k][tcol + 4];
            float ra[8] = {a0.x, a0.y, a0.z, a0.w, a1.x, a1.y, a1.z, a1.w};
            float rb[8] = {b0.x, b0.y, b0.z, b0.w, b1.x, b1.y, b1.z, b1.w};
#pragma unroll
            for (int i = 0; i < 8; i++)
#pragma unroll
                for (int j = 0; j < 8; j++)
                    acc[i][j] = fmaf(ra[i], rb[j], acc[i][j]);
        }
        __syncthreads();
    }

    // ---- C store ----
#pragma unroll
    for (int i = 0; i < 8; i++) {
        int grow = brow + trow + i;
        if (grow < M) {
            if (F16OUT) {
                uint32_t pk[4];
#pragma unroll
                for (int jj = 0; jj < 4; jj++) {
                    __half2 t2 = __floats2half2_rn(acc[i][2 * jj], acc[i][2 * jj + 1]);
                    pk[jj] = *reinterpret_cast<uint32_t*>(&t2);
                }
                uint4 u = {pk[0], pk[1], pk[2], pk[3]};
                *(uint4*)&Ch[(size_t)grow * NN + bcol + tcol] = u;
            } else {
                *(float4*)&Cf[(size_t)grow * NN + bcol + tcol] =
                    make_float4(acc[i][0], acc[i][1], acc[i][2], acc[i][3]);
                *(float4*)&Cf[(size_t)grow * NN + bcol + tcol + 4] =
                    make_float4(acc[i][4], acc[i][5], acc[i][6], acc[i][7]);
            }
        }
    }

    // ---- fused attention scores ----
    float a_s[8], a_d[8];
#pragma unroll
    for (int j = 0; j < 8; j++) {
        a_s[j] = va_s[bcol + tcol + j];
        a_d[j] = va_d[bcol + tcol + j];
    }
    float ps[8], pd[8];
#pragma unroll
    for (int i = 0; i < 8; i++) {
        float s = 0.f, d = 0.f;
#pragma unroll
        for (int j = 0; j < 8; j++) {
            s = fmaf(acc[i][j], a_s[j], s);
            d = fmaf(acc[i][j], a_d[j], d);
        }
        ps[i] = s;
        pd[i] = d;
    }
    // head width: 256/4=64 cols -> 8 lanes; 128/1=128 cols -> 16 lanes
    constexpr int G = (HEADS == 4) ? 8 : 16;
#pragma unroll
    for (int off = 1; off < G; off <<= 1) {
#pragma unroll
        for (int i = 0; i < 8; i++) {
            ps[i] += __shfl_xor_sync(0xffffffffu, ps[i], off);
            pd[i] += __shfl_xor_sync(0xffffffffu, pd[i], off);
        }
    }
    if ((tid & (G - 1)) == 0) {
        int head = (HEADS == 4) ? ((bcol + tcol) >> 6) : 0;
#pragma unroll
        for (int i = 0; i < 8; i++) {
            int grow = brow + trow + i;
            if (grow < M) {
                es[grow * HEADS + head] = ps[i];
                ed[grow * HEADS + head] = pd[i];
            }
        }
    }
}

__global__ __launch_bounds__(256) void gemm1_k(const float* __restrict__ x,
                                               const float* __restrict__ W1,
                                               const float* __restrict__ as1,
                                               const float* __restrict__ ad1, int M) {
    gemm_fused_body<256, 128, 4, true>(M, x, W1, nullptr, g_h1h, as1, ad1,
                                       g_es1, g_ed1);
}
__global__ __launch_bounds__(256) void gemm2_k(const float* __restrict__ W2,
                                               const float* __restrict__ as2,
                                               const float* __restrict__ ad2, int M) {
    gemm_fused_body<128, 256, 1, false>(M, g_out1, W2, g_h2, nullptr, as2, ad2,
                                        g_es2, g_ed2);
}

// ---------------- CSR build ----------------
__global__ void zeroc_k(int N) {
    int i = blockIdx.x * blockDim.x + threadIdx.x;
    if (i < N) g_cnt[i] = 0;
}
__global__ void count_k(const int* __restrict__ ei, int E, int Et) {
    int e = blockIdx.x * blockDim.x + threadIdx.x;
    if (e >= Et) return;
    int d = (e < E) ? ei[E + e] : (e - E);
    atomicAdd(&g_cnt[d], 1);
}
__global__ __launch_bounds__(1024) void scan1_k(int N) {
    __shared__ int sh[1024];
    int i = blockIdx.x * 1024 + threadIdx.x;
    int v = (i < N) ? g_cnt[i] : 0;
    sh[threadIdx.x] = v;
    __syncthreads();
#pragma unroll
    for (int off = 1; off < 1024; off <<= 1) {
        int t = (threadIdx.x >= off) ? sh[threadIdx.x - off] : 0;
        __syncthreads();
        sh[threadIdx.x] += t;
        __syncthreads();
    }
    if (i < N) g_scan[i] = sh[threadIdx.x];
    if (threadIdx.x == 1023) g_bsum[blockIdx.x] = sh[1023];
}
__global__ void scan2_k(int nb) {
    __shared__ int sh[64];
    int v = (threadIdx.x < nb) ? g_bsum[threadIdx.x] : 0;
    sh[threadIdx.x] = v;
    __syncthreads();
#pragma unroll
    for (int off = 1; off < 64; off <<= 1) {
        int t = (threadIdx.x >= off) ? sh[threadIdx.x - off] : 0;
        __syncthreads();
        sh[threadIdx.x] += t;
        __syncthreads();
    }
    if (threadIdx.x < nb)
        g_bsum[threadIdx.x] = threadIdx.x ? sh[threadIdx.x - 1] : 0;
}
__global__ void scan3_k(int N, int Et) {
    int i = blockIdx.x * blockDim.x + threadIdx.x;
    if (i >= N) return;
    int excl = g_scan[i] - g_cnt[i] + g_bsum[i >> 10];
    g_rp[i] = excl;
    g_cur[i] = excl;
    if (i == 0) g_rp[N] = Et;
}
__global__ void fill_k(const int* __restrict__ ei, int E, int Et) {
    int e = blockIdx.x * blockDim.x + threadIdx.x;
    if (e >= Et) return;
    int s, d;
    if (e < E) { s = ei[e]; d = ei[E + e]; } else { s = e - E; d = s; }
    int pos = atomicAdd(&g_cur[d], 1);
    g_csr[pos] = s;
}

// ---------------- fused gather aggregation (warp per destination node) --------
// out1[d] = elu( (sum_e p_e * h1[src_e]) / (sum_e p_e) + b1 ), h1 gathered fp16
__device__ __forceinline__ void agg1_edge(int s, float4 ed4, int lane, int h,
                                          float* a, float4& z) {
    float4 es4 = *(const float4*)&g_es1[s * 4];
    float t;
    float4 p;
    t = es4.x + ed4.x; t = t > 0.f ? t : 0.2f * t; p.x = __expf(t);
    t = es4.y + ed4.y; t = t > 0.f ? t : 0.2f * t; p.y = __expf(t);
    t = es4.z + ed4.z; t = t > 0.f ? t : 0.2f * t; p.z = __expf(t);
    t = es4.w + ed4.w; t = t > 0.f ? t : 0.2f * t; p.w = __expf(t);
    z.x += p.x; z.y += p.y; z.z += p.z; z.w += p.w;
    float ph = h == 0 ? p.x : (h == 1 ? p.y : (h == 2 ? p.z : p.w));
    uint4 raw = *(const uint4*)&g_h1h[(size_t)s * 256 + lane * 8];
    uint32_t w0 = raw.x, w1 = raw.y, w2 = raw.z, w3 = raw.w;
    float2 f0 = __half22float2(*reinterpret_cast<__half2*>(&w0));
    float2 f1 = __half22float2(*reinterpret_cast<__half2*>(&w1));
    float2 f2 = __half22float2(*reinterpret_cast<__half2*>(&w2));
    float2 f3 = __half22float2(*reinterpret_cast<__half2*>(&w3));
    a[0] = fmaf(ph, f0.x, a[0]); a[1] = fmaf(ph, f0.y, a[1]);
    a[2] = fmaf(ph, f1.x, a[2]); a[3] = fmaf(ph, f1.y, a[3]);
    a[4] = fmaf(ph, f2.x, a[4]); a[5] = fmaf(ph, f2.y, a[5]);
    a[6] = fmaf(ph, f3.x, a[6]); a[7] = fmaf(ph, f3.y, a[7]);
}

__global__ __launch_bounds__(256) void agg1_k(const float* __restrict__ b1, int N) {
    int d = (blockIdx.x * blockDim.x + threadIdx.x) >> 5;
    int lane = threadIdx.x & 31;
    if (d >= N) return;
    float4 ed4 = *(const float4*)&g_ed1[d * 4];
    int beg = g_rp[d], end = g_rp[d + 1];
    int h = lane >> 3;  // lane covers cols [lane*8, lane*8+8); head = col/64
    float a[8] = {0, 0, 0, 0, 0, 0, 0, 0};
    float4 z = {0, 0, 0, 0};
    int i = beg;
    for (; i + 1 < end; i += 2) {
        int s0 = g_csr[i], s1 = g_csr[i + 1];
        agg1_edge(s0, ed4, lane, h, a, z);
        agg1_edge(s1, ed4, lane, h, a, z);
    }
    if (i < end) agg1_edge(g_csr[i], ed4, lane, h, a, z);

    float zh = h == 0 ? z.x : (h == 1 ? z.y : (h == 2 ? z.z : z.w));
    float inv = 1.f / zh;
    int col = lane * 8;
    float4 bb0 = *(const float4*)&b1[col];
    float4 bb1 = *(const float4*)&b1[col + 4];
    float4 o0, o1;
    float v;
    v = a[0] * inv + bb0.x; o0.x = v > 0.f ? v : expm1f(v);
    v = a[1] * inv + bb0.y; o0.y = v > 0.f ? v : expm1f(v);
    v = a[2] * inv + bb0.z; o0.z = v > 0.f ? v : expm1f(v);
    v = a[3] * inv + bb0.w; o0.w = v > 0.f ? v : expm1f(v);
    v = a[4] * inv + bb1.x; o1.x = v > 0.f ? v : expm1f(v);
    v = a[5] * inv + bb1.y; o1.y = v > 0.f ? v : expm1f(v);
    v = a[6] * inv + bb1.z; o1.z = v > 0.f ? v : expm1f(v);
    v = a[7] * inv + bb1.w; o1.w = v > 0.f ? v : expm1f(v);
    float* outr = &g_out1[(size_t)d * 256 + col];
    *(float4*)outr = o0;
    *(float4*)(outr + 4) = o1;
}

// out[d] = (sum_e p_e * h2[src_e]) / (sum_e p_e) + b2   (fp32: final output)
__global__ __launch_bounds__(256) void agg2_k(float* __restrict__ out,
                                              const float* __restrict__ b2, int N) {
    int d = (blockIdx.x * blockDim.x + threadIdx.x) >> 5;
    int lane = threadIdx.x & 31;
    if (d >= N) return;
    float edv = g_ed2[d];
    int beg = g_rp[d], end = g_rp[d + 1];
    float4 acc = {0, 0, 0, 0};
    float z = 0.f;
    for (int i = beg; i < end; i++) {
        int s = g_csr[i];
        float t = g_es2[s] + edv;
        t = t > 0.f ? t : 0.2f * t;
        float p = __expf(t);
        z += p;
        float4 vv = *(const float4*)&g_h2[(size_t)s * 128 + lane * 4];
        acc.x = fmaf(p, vv.x, acc.x); acc.y = fmaf(p, vv.y, acc.y);
        acc.z = fmaf(p, vv.z, acc.z); acc.w = fmaf(p, vv.w, acc.w);
    }
    float inv = 1.f / z;
    int col = lane * 4;
    float4 bb = *(const float4*)&b2[col];
    float4 o;
    o.x = acc.x * inv + bb.x; o.y = acc.y * inv + bb.y;
    o.z = acc.z * inv + bb.z; o.w = acc.w * inv + bb.w;
    *(float4*)&out[(size_t)d * 128 + col] = o;
}

// ---------------- launch ----------------
extern "C" void kernel_launch(void* const* d_in, const int* in_sizes, int n_in,
                              void* d_out, int out_size) {
    const float* x   = (const float*)d_in[0];
    const int*   ei  = (const int*)d_in[1];
    const float* W1  = (const float*)d_in[2];
    const float* as1 = (const float*)d_in[3];
    const float* ad1 = (const float*)d_in[4];
    const float* b1  = (const float*)d_in[5];
    const float* W2  = (const float*)d_in[6];
    const float* as2 = (const float*)d_in[7];
    const float* ad2 = (const float*)d_in[8];
    const float* b2  = (const float*)d_in[9];
    float* out = (float*)d_out;

    int N  = in_sizes[0] / 128;  // in_dim = 128
    int E  = in_sizes[1] / 2;
    int Et = E + N;
    int nb = (N + 1023) / 1024;

    // lazily-created side stream + fork/join events (created on the
    // correctness call, which precedes graph capture)
    static cudaStream_t s1 = nullptr;
    static cudaEvent_t ev0 = nullptr, ev1 = nullptr;
    if (!s1) {
        cudaStreamCreateWithFlags(&s1, cudaStreamNonBlocking);
        cudaEventCreateWithFlags(&ev0, cudaEventDisableTiming);
        cudaEventCreateWithFlags(&ev1, cudaEventDisableTiming);
    }

    // ---- fork: CSR build on s1, overlapped with gemm1 on the main stream ----
    cudaEventRecord(ev0, 0);
    cudaStreamWaitEvent(s1, ev0, 0);
    zeroc_k<<<(N + 255) / 256, 256, 0, s1>>>(N);
    count_k<<<(Et + 255) / 256, 256, 0, s1>>>(ei, E, Et);
    scan1_k<<<nb, 1024, 0, s1>>>(N);
    scan2_k<<<1, 64, 0, s1>>>(nb);
    scan3_k<<<(N + 255) / 256, 256, 0, s1>>>(N, Et);
    fill_k<<<(Et + 255) / 256, 256, 0, s1>>>(ei, E, Et);
    cudaEventRecord(ev1, s1);

    // ---- Layer 1 (main stream) ----
    gemm1_k<<<dim3(2, (N + 127) / 128), 256>>>(x, W1, as1, ad1, N);
    cudaStreamWaitEvent(0, ev1, 0);  // join CSR before aggregation
    agg1_k<<<(N * 32 + 255) / 256, 256>>>(b1, N);

    // ---- Layer 2 ----
    gemm2_k<<<dim3(1, (N + 127) / 128), 256>>>(W2, as2, ad2, N);
    agg2_k<<<(N * 32 + 255) / 256, 256>>>(out, b2, N);
}

// round 10
// speedup vs baseline: 2.6374x; 1.2480x over previous
#include <cuda_runtime.h>
#include <cuda_fp16.h>
#include <cstdint>
#include <math.h>

// Problem-shape constants (from reference setup_inputs)
#define NMAX 50000
#define EMAX 800000
#define ETMAX (EMAX + NMAX)

// ---------------- device scratch (no allocations allowed) ----------------
__device__ __align__(16) __half g_h1h[NMAX * 256];  // x@W1 as fp16 (gather src)
__device__ __align__(16) float g_out1[NMAX * 256];  // layer1 out (post-ELU)
__device__ __align__(16) float g_h2[NMAX * 128];    // out1 @ W2
__device__ __align__(16) float g_es1[NMAX * 4];
__device__ __align__(16) float g_ed1[NMAX * 4];
__device__ __align__(16) float g_es2[NMAX];
__device__ __align__(16) float g_ed2[NMAX];

// CSR-by-destination (built once per launch, reused by both layers)
__device__ int g_cnt[NMAX];
__device__ int g_scan[NMAX];
__device__ int g_bsum[64];
__device__ int g_rp[NMAX + 1];
__device__ int g_cur[NMAX];
__device__ int g_csr[ETMAX];

// ---------------- tf32 tensor-core helpers ----------------
__device__ __forceinline__ uint32_t f2tf32(float f) {
    uint32_t r;
    asm("cvt.rna.tf32.f32 %0, %1;" : "=r"(r) : "f"(f));
    return r;
}
__device__ __forceinline__ void mma_tf32(float* c, const uint32_t* a,
                                         uint32_t b0, uint32_t b1) {
    asm volatile(
        "mma.sync.aligned.m16n8k8.row.col.f32.tf32.tf32.f32 "
        "{%0,%1,%2,%3}, {%4,%5,%6,%7}, {%8,%9}, {%0,%1,%2,%3};"
        : "+f"(c[0]), "+f"(c[1]), "+f"(c[2]), "+f"(c[3])
        : "r"(a[0]), "r"(a[1]), "r"(a[2]), "r"(a[3]), "r"(b0), "r"(b1));
}

// ---------------- tf32 tensor-core GEMM + fused score epilogue ----------------
// C[M,NN] = A[M,KK] @ B[KK,NN]. Block 128x128, BK=32, 8 warps (4m x 2n),
// each warp 32x64 = 2(m) x 8(n) m16n8k8 tiles. Pitch-36 smem (conflict-free).
// Epilogue computes es/ed = C . a_src/a_dst from exact fp32 accumulators.
#define PITCH 36
template <int NN, int KK, int HEADS, bool F16OUT>
__device__ __forceinline__ void gemm_tc_body(
    int M, const float* __restrict__ A, const float* __restrict__ B,
    float* __restrict__ Cf, __half* __restrict__ Ch,
    const float* __restrict__ va_s, const float* __restrict__ va_d,
    float* __restrict__ es, float* __restrict__ ed) {
    __shared__ uint32_t As[128 * PITCH];
    __shared__ uint32_t Bst[128 * PITCH];      // transposed: [n][k]
    __shared__ float sred[2][2][128];          // [s/d][warp_n][row] (HEADS==1)

    const int tid = threadIdx.x;
    const int wid = tid >> 5;
    const int lane = tid & 31;
    const int lq = lane >> 2;   // groupID
    const int lr = lane & 3;    // threadID_in_group
    const int warp_m = wid >> 1;
    const int warp_n = wid & 1;
    const int brow = blockIdx.y * 128;
    const int bcol = blockIdx.x * 128;

    // staging coords
    const int ar = tid >> 1;                 // A row 0..127
    const int ac = (tid & 1) * 16;           // A col base
    const int bkr = tid >> 3;                // B k-row 0..31
    const int bnc = (tid & 7) * 16;          // B n base

    float acc[2][8][4] = {};

    for (int k0 = 0; k0 < KK; k0 += 32) {
        __syncthreads();
        // ---- stage A (convert fp32 -> tf32) ----
        {
            int grow = brow + ar;
            const float* ap = &A[(size_t)grow * KK + k0 + ac];
#pragma unroll
            for (int i = 0; i < 4; i++) {
                float4 v = (grow < M) ? *(const float4*)(ap + 4 * i)
                                      : make_float4(0.f, 0.f, 0.f, 0.f);
                uint32_t* dst = &As[ar * PITCH + ac + 4 * i];
                dst[0] = f2tf32(v.x); dst[1] = f2tf32(v.y);
                dst[2] = f2tf32(v.z); dst[3] = f2tf32(v.w);
            }
        }
        // ---- stage B transposed ----
        {
            const float* bp = &B[(size_t)(k0 + bkr) * NN + bcol + bnc];
#pragma unroll
            for (int i = 0; i < 4; i++) {
                float4 v = *(const float4*)(bp + 4 * i);
                Bst[(bnc + 4 * i + 0) * PITCH + bkr] = f2tf32(v.x);
                Bst[(bnc + 4 * i + 1) * PITCH + bkr] = f2tf32(v.y);
                Bst[(bnc + 4 * i + 2) * PITCH + bkr] = f2tf32(v.z);
                Bst[(bnc + 4 * i + 3) * PITCH + bkr] = f2tf32(v.w);
            }
        }
        __syncthreads();

        // ---- compute: 4 k-steps of 8 ----
#pragma unroll
        for (int kt = 0; kt < 4; kt++) {
            uint32_t afr[2][4];
#pragma unroll
            for (int mt = 0; mt < 2; mt++) {
                int r = warp_m * 32 + mt * 16 + lq;
                int kc = kt * 8 + lr;
                afr[mt][0] = As[r * PITCH + kc];
                afr[mt][1] = As[(r + 8) * PITCH + kc];
                afr[mt][2] = As[r * PITCH + kc + 4];
                afr[mt][3] = As[(r + 8) * PITCH + kc + 4];
            }
#pragma unroll
            for (int nt = 0; nt < 8; nt++) {
                int n = warp_n * 64 + nt * 8 + lq;
                int kc = kt * 8 + lr;
                uint32_t b0 = Bst[n * PITCH + kc];
                uint32_t b1 = Bst[n * PITCH + kc + 4];
                mma_tf32(acc[0][nt], afr[0], b0, b1);
                mma_tf32(acc[1][nt], afr[1], b0, b1);
            }
        }
    }

    // ---- C store ----
#pragma unroll
    for (int mt = 0; mt < 2; mt++) {
        int r0 = brow + warp_m * 32 + mt * 16 + lq;
        int r1 = r0 + 8;
#pragma unroll
        for (int nt = 0; nt < 8; nt++) {
            int c = bcol + warp_n * 64 + nt * 8 + lr * 2;
            if (F16OUT) {
                if (r0 < M) {
                    __half2 h = __floats2half2_rn(acc[mt][nt][0], acc[mt][nt][1]);
                    *(__half2*)&Ch[(size_t)r0 * NN + c] = h;
                }
                if (r1 < M) {
                    __half2 h = __floats2half2_rn(acc[mt][nt][2], acc[mt][nt][3]);
                    *(__half2*)&Ch[(size_t)r1 * NN + c] = h;
                }
            } else {
                if (r0 < M)
                    *(float2*)&Cf[(size_t)r0 * NN + c] =
                        make_float2(acc[mt][nt][0], acc[mt][nt][1]);
                if (r1 < M)
                    *(float2*)&Cf[(size_t)r1 * NN + c] =
                        make_float2(acc[mt][nt][2], acc[mt][nt][3]);
            }
        }
    }

    // ---- fused attention scores ----
    float cs[8][2], cd[8][2];
#pragma unroll
    for (int nt = 0; nt < 8; nt++) {
        int c = bcol + warp_n * 64 + nt * 8 + lr * 2;
        cs[nt][0] = va_s[c]; cs[nt][1] = va_s[c + 1];
        cd[nt][0] = va_d[c]; cd[nt][1] = va_d[c + 1];
    }
#pragma unroll
    for (int mt = 0; mt < 2; mt++) {
        float s0 = 0.f, d0 = 0.f, s1 = 0.f, d1 = 0.f;
#pragma unroll
        for (int nt = 0; nt < 8; nt++) {
            s0 = fmaf(acc[mt][nt][0], cs[nt][0], fmaf(acc[mt][nt][1], cs[nt][1], s0));
            d0 = fmaf(acc[mt][nt][0], cd[nt][0], fmaf(acc[mt][nt][1], cd[nt][1], d0));
            s1 = fmaf(acc[mt][nt][2], cs[nt][0], fmaf(acc[mt][nt][3], cs[nt][1], s1));
            d1 = fmaf(acc[mt][nt][2], cd[nt][0], fmaf(acc[mt][nt][3], cd[nt][1], d1));
        }
        // reduce over the 4 lanes of the quad (covers warp's 64 cols)
#pragma unroll
        for (int o = 1; o < 4; o <<= 1) {
            s0 += __shfl_xor_sync(0xffffffffu, s0, o);
            d0 += __shfl_xor_sync(0xffffffffu, d0, o);
            s1 += __shfl_xor_sync(0xffffffffu, s1, o);
            d1 += __shfl_xor_sync(0xffffffffu, d1, o);
        }
        if (lr == 0) {
            int rl0 = warp_m * 32 + mt * 16 + lq;      // local row
            int rl1 = rl0 + 8;
            if (HEADS == 4) {                          // 64-col head == warp width
                int head = blockIdx.x * 2 + warp_n;
                int g0 = brow + rl0, g1 = brow + rl1;
                if (g0 < M) { es[g0 * 4 + head] = s0; ed[g0 * 4 + head] = d0; }
                if (g1 < M) { es[g1 * 4 + head] = s1; ed[g1 * 4 + head] = d1; }
            } else {                                   // single head: smem combine
                sred[0][warp_n][rl0] = s0; sred[1][warp_n][rl0] = d0;
                sred[0][warp_n][rl1] = s1; sred[1][warp_n][rl1] = d1;
            }
        }
    }
    if (HEADS == 1) {
        __syncthreads();
        if (tid < 128) {
            int g = brow + tid;
            if (g < M) {
                es[g] = sred[0][0][tid] + sred[0][1][tid];
                ed[g] = sred[1][0][tid] + sred[1][1][tid];
            }
        }
    }
}

__global__ __launch_bounds__(256) void gemm1_k(const float* __restrict__ x,
                                               const float* __restrict__ W1,
                                               const float* __restrict__ as1,
                                               const float* __restrict__ ad1, int M) {
    gemm_tc_body<256, 128, 4, true>(M, x, W1, nullptr, g_h1h, as1, ad1,
                                    g_es1, g_ed1);
}
__global__ __launch_bounds__(256) void gemm2_k(const float* __restrict__ W2,
                                               const float* __restrict__ as2,
                                               const float* __restrict__ ad2, int M) {
    gemm_tc_body<128, 256, 1, false>(M, g_out1, W2, g_h2, nullptr, as2, ad2,
                                     g_es2, g_ed2);
}

// ---------------- CSR build ----------------
__global__ void zeroc_k(int N) {
    int i = blockIdx.x * blockDim.x + threadIdx.x;
    if (i < N) g_cnt[i] = 0;
}
__global__ void count_k(const int* __restrict__ ei, int E, int Et) {
    int e = blockIdx.x * blockDim.x + threadIdx.x;
    if (e >= Et) return;
    int d = (e < E) ? ei[E + e] : (e - E);
    atomicAdd(&g_cnt[d], 1);
}
__global__ __launch_bounds__(1024) void scan1_k(int N) {
    __shared__ int sh[1024];
    int i = blockIdx.x * 1024 + threadIdx.x;
    int v = (i < N) ? g_cnt[i] : 0;
    sh[threadIdx.x] = v;
    __syncthreads();
#pragma unroll
    for (int off = 1; off < 1024; off <<= 1) {
        int t = (threadIdx.x >= off) ? sh[threadIdx.x - off] : 0;
        __syncthreads();
        sh[threadIdx.x] += t;
        __syncthreads();
    }
    if (i < N) g_scan[i] = sh[threadIdx.x];
    if (threadIdx.x == 1023) g_bsum[blockIdx.x] = sh[1023];
}
__global__ void scan2_k(int nb) {
    __shared__ int sh[64];
    int v = (threadIdx.x < nb) ? g_bsum[threadIdx.x] : 0;
    sh[threadIdx.x] = v;
    __syncthreads();
#pragma unroll
    for (int off = 1; off < 64; off <<= 1) {
        int t = (threadIdx.x >= off) ? sh[threadIdx.x - off] : 0;
        __syncthreads();
        sh[threadIdx.x] += t;
        __syncthreads();
    }
    if (threadIdx.x < nb)
        g_bsum[threadIdx.x] = threadIdx.x ? sh[threadIdx.x - 1] : 0;
}
__global__ void scan3_k(int N, int Et) {
    int i = blockIdx.x * blockDim.x + threadIdx.x;
    if (i >= N) return;
    int excl = g_scan[i] - g_cnt[i] + g_bsum[i >> 10];
    g_rp[i] = excl;
    g_cur[i] = excl;
    if (i == 0) g_rp[N] = Et;
}
__global__ void fill_k(const int* __restrict__ ei, int E, int Et) {
    int e = blockIdx.x * blockDim.x + threadIdx.x;
    if (e >= Et) return;
    int s, d;
    if (e < E) { s = ei[e]; d = ei[E + e]; } else { s = e - E; d = s; }
    int pos = atomicAdd(&g_cur[d], 1);
    g_csr[pos] = s;
}

// ---------------- fused gather aggregation (warp per destination node) --------
// out1[d] = elu( (sum_e p_e * h1[src_e]) / (sum_e p_e) + b1 ), h1 gathered fp16
__device__ __forceinline__ void agg1_edge(int s, float4 ed4, int lane, int h,
                                          float* a, float4& z) {
    float4 es4 = *(const float4*)&g_es1[s * 4];
    float t;
    float4 p;
    t = es4.x + ed4.x; t = t > 0.f ? t : 0.2f * t; p.x = __expf(t);
    t = es4.y + ed4.y; t = t > 0.f ? t : 0.2f * t; p.y = __expf(t);
    t = es4.z + ed4.z; t = t > 0.f ? t : 0.2f * t; p.z = __expf(t);
    t = es4.w + ed4.w; t = t > 0.f ? t : 0.2f * t; p.w = __expf(t);
    z.x += p.x; z.y += p.y; z.z += p.z; z.w += p.w;
    float ph = h == 0 ? p.x : (h == 1 ? p.y : (h == 2 ? p.z : p.w));
    uint4 raw = *(const uint4*)&g_h1h[(size_t)s * 256 + lane * 8];
    uint32_t w0 = raw.x, w1 = raw.y, w2 = raw.z, w3 = raw.w;
    float2 f0 = __half22float2(*reinterpret_cast<__half2*>(&w0));
    float2 f1 = __half22float2(*reinterpret_cast<__half2*>(&w1));
    float2 f2 = __half22float2(*reinterpret_cast<__half2*>(&w2));
    float2 f3 = __half22float2(*reinterpret_cast<__half2*>(&w3));
    a[0] = fmaf(ph, f0.x, a[0]); a[1] = fmaf(ph, f0.y, a[1]);
    a[2] = fmaf(ph, f1.x, a[2]); a[3] = fmaf(ph, f1.y, a[3]);
    a[4] = fmaf(ph, f2.x, a[4]); a[5] = fmaf(ph, f2.y, a[5]);
    a[6] = fmaf(ph, f3.x, a[6]); a[7] = fmaf(ph, f3.y, a[7]);
}

__global__ __launch_bounds__(256) void agg1_k(const float* __restrict__ b1, int N) {
    int d = (blockIdx.x * blockDim.x + threadIdx.x) >> 5;
    int lane = threadIdx.x & 31;
    if (d >= N) return;
    float4 ed4 = *(const float4*)&g_ed1[d * 4];
    int beg = g_rp[d], end = g_rp[d + 1];
    int h = lane >> 3;  // lane covers cols [lane*8, lane*8+8); head = col/64
    float a[8] = {0, 0, 0, 0, 0, 0, 0, 0};
    float4 z = {0, 0, 0, 0};
    int i = beg;
    for (; i + 1 < end; i += 2) {
        int s0 = g_csr[i], s1 = g_csr[i + 1];
        agg1_edge(s0, ed4, lane, h, a, z);
        agg1_edge(s1, ed4, lane, h, a, z);
    }
    if (i < end) agg1_edge(g_csr[i], ed4, lane, h, a, z);

    float zh = h == 0 ? z.x : (h == 1 ? z.y : (h == 2 ? z.z : z.w));
    float inv = 1.f / zh;
    int col = lane * 8;
    float4 bb0 = *(const float4*)&b1[col];
    float4 bb1 = *(const float4*)&b1[col + 4];
    float4 o0, o1;
    float v;
    v = a[0] * inv + bb0.x; o0.x = v > 0.f ? v : expm1f(v);
    v = a[1] * inv + bb0.y; o0.y = v > 0.f ? v : expm1f(v);
    v = a[2] * inv + bb0.z; o0.z = v > 0.f ? v : expm1f(v);
    v = a[3] * inv + bb0.w; o0.w = v > 0.f ? v : expm1f(v);
    v = a[4] * inv + bb1.x; o1.x = v > 0.f ? v : expm1f(v);
    v = a[5] * inv + bb1.y; o1.y = v > 0.f ? v : expm1f(v);
    v = a[6] * inv + bb1.z; o1.z = v > 0.f ? v : expm1f(v);
    v = a[7] * inv + bb1.w; o1.w = v > 0.f ? v : expm1f(v);
    float* outr = &g_out1[(size_t)d * 256 + col];
    *(float4*)outr = o0;
    *(float4*)(outr + 4) = o1;
}

// out[d] = (sum_e p_e * h2[src_e]) / (sum_e p_e) + b2   (fp32: final output)
__global__ __launch_bounds__(256) void agg2_k(float* __restrict__ out,
                                              const float* __restrict__ b2, int N) {
    int d = (blockIdx.x * blockDim.x + threadIdx.x) >> 5;
    int lane = threadIdx.x & 31;
    if (d >= N) return;
    float edv = g_ed2[d];
    int beg = g_rp[d], end = g_rp[d + 1];
    float4 acc = {0, 0, 0, 0};
    float z = 0.f;
    for (int i = beg; i < end; i++) {
        int s = g_csr[i];
        float t = g_es2[s] + edv;
        t = t > 0.f ? t : 0.2f * t;
        float p = __expf(t);
        z += p;
        float4 vv = *(const float4*)&g_h2[(size_t)s * 128 + lane * 4];
        acc.x = fmaf(p, vv.x, acc.x); acc.y = fmaf(p, vv.y, acc.y);
        acc.z = fmaf(p, vv.z, acc.z); acc.w = fmaf(p, vv.w, acc.w);
    }
    float inv = 1.f / z;
    int col = lane * 4;
    float4 bb = *(const float4*)&b2[col];
    float4 o;
    o.x = acc.x * inv + bb.x; o.y = acc.y * inv + bb.y;
    o.z = acc.z * inv + bb.z; o.w = acc.w * inv + bb.w;
    *(float4*)&out[(size_t)d * 128 + col] = o;
}

// ---------------- launch ----------------
extern "C" void kernel_launch(void* const* d_in, const int* in_sizes, int n_in,
                              void* d_out, int out_size) {
    const float* x   = (const float*)d_in[0];
    const int*   ei  = (const int*)d_in[1];
    const float* W1  = (const float*)d_in[2];
    const float* as1 = (const float*)d_in[3];
    const float* ad1 = (const float*)d_in[4];
    const float* b1  = (const float*)d_in[5];
    const float* W2  = (const float*)d_in[6];
    const float* as2 = (const float*)d_in[7];
    const float* ad2 = (const float*)d_in[8];
    const float* b2  = (const float*)d_in[9];
    float* out = (float*)d_out;

    int N  = in_sizes[0] / 128;  // in_dim = 128
    int E  = in_sizes[1] / 2;
    int Et = E + N;
    int nb = (N + 1023) / 1024;
    int gy = (N + 127) / 128;

    // lazily-created side stream + fork/join events (created on the
    // correctness call, which precedes graph capture)
    static cudaStream_t s1 = nullptr;
    static cudaEvent_t ev0 = nullptr, ev1 = nullptr;
    if (!s1) {
        cudaStreamCreateWithFlags(&s1, cudaStreamNonBlocking);
        cudaEventCreateWithFlags(&ev0, cudaEventDisableTiming);
        cudaEventCreateWithFlags(&ev1, cudaEventDisableTiming);
    }

    // ---- fork: CSR build on s1, overlapped with gemm1 on the main stream ----
    cudaEventRecord(ev0, 0);
    cudaStreamWaitEvent(s1, ev0, 0);
    zeroc_k<<<(N + 255) / 256, 256, 0, s1>>>(N);
    count_k<<<(Et + 255) / 256, 256, 0, s1>>>(ei, E, Et);
    scan1_k<<<nb, 1024, 0, s1>>>(N);
    scan2_k<<<1, 64, 0, s1>>>(nb);
    scan3_k<<<(N + 255) / 256, 256, 0, s1>>>(N, Et);
    fill_k<<<(Et + 255) / 256, 256, 0, s1>>>(ei, E, Et);
    cudaEventRecord(ev1, s1);

    // ---- Layer 1 (main stream) ----
    gemm1_k<<<dim3(2, gy), 256>>>(x, W1, as1, ad1, N);
    cudaStreamWaitEvent(0, ev1, 0);  // join CSR before aggregation
    agg1_k<<<(N * 32 + 255) / 256, 256>>>(b1, N);

    // ---- Layer 2 ----
    gemm2_k<<<dim3(1, gy), 256>>>(W2, as2, ad2, N);
    agg2_k<<<(N * 32 + 255) / 256, 256>>>(out, b2, N);
}

// round 12
// speedup vs baseline: 2.6456x; 1.0031x over previous
#include <cuda_runtime.h>
#include <cuda_fp16.h>
#include <cstdint>
#include <math.h>

// Problem-shape constants (from reference setup_inputs)
#define NMAX 50000
#define EMAX 800000
#define ETMAX (EMAX + NMAX)

// ---------------- device scratch (no allocations allowed) ----------------
__device__ __align__(16) __half g_h1h[NMAX * 256];  // x@W1 as fp16 (gather src)
__device__ __align__(16) float g_out1[NMAX * 256];  // layer1 out (post-ELU)
__device__ __align__(16) __half g_h2h[NMAX * 128];  // out1@W2 as fp16 (gather src)
__device__ __align__(16) float g_es1[NMAX * 4];
__device__ __align__(16) float g_ed1[NMAX * 4];
__device__ __align__(16) float g_es2[NMAX];
__device__ __align__(16) float g_ed2[NMAX];

// CSR-by-destination (built once per launch, reused by both layers)
__device__ int g_cnt[NMAX];   // invariant: zero at launch entry (static init;
                              // scan3_k re-zeroes it after reading)
__device__ int g_scan[NMAX];
__device__ int g_bsum[64];
__device__ int g_rp[NMAX + 1];
__device__ int g_cur[NMAX];
__device__ int g_csr[ETMAX];

// ---------------- tf32 tensor-core helpers ----------------
__device__ __forceinline__ uint32_t f2tf32(float f) {
    uint32_t r;
    asm("cvt.rna.tf32.f32 %0, %1;" : "=r"(r) : "f"(f));
    return r;
}
__device__ __forceinline__ void mma_tf32(float* c, const uint32_t* a,
                                         uint32_t b0, uint32_t b1) {
    asm volatile(
        "mma.sync.aligned.m16n8k8.row.col.f32.tf32.tf32.f32 "
        "{%0,%1,%2,%3}, {%4,%5,%6,%7}, {%8,%9}, {%0,%1,%2,%3};"
        : "+f"(c[0]), "+f"(c[1]), "+f"(c[2]), "+f"(c[3])
        : "r"(a[0]), "r"(a[1]), "r"(a[2]), "r"(a[3]), "r"(b0), "r"(b1));
}

// ---------------- tf32 tensor-core GEMM + fused score epilogue ----------------
// C[M,NN] = A[M,KK] @ B[KK,NN]. Block 128x128, BK=32, 8 warps (4m x 2n),
// each warp 32x64 = 2(m) x 8(n) m16n8k8 tiles. Pitch-36 smem (conflict-free).
// Epilogue computes es/ed = C . a_src/a_dst from exact fp32 accumulators.
#define PITCH 36
template <int NN, int KK, int HEADS, bool F16OUT>
__device__ __forceinline__ void gemm_tc_body(
    int M, const float* __restrict__ A, const float* __restrict__ B,
    float* __restrict__ Cf, __half* __restrict__ Ch,
    const float* __restrict__ va_s, const float* __restrict__ va_d,
    float* __restrict__ es, float* __restrict__ ed) {
    __shared__ uint32_t As[128 * PITCH];
    __shared__ uint32_t Bst[128 * PITCH];      // transposed: [n][k]
    __shared__ float sred[2][2][128];          // [s/d][warp_n][row] (HEADS==1)

    const int tid = threadIdx.x;
    const int wid = tid >> 5;
    const int lane = tid & 31;
    const int lq = lane >> 2;   // groupID
    const int lr = lane & 3;    // threadID_in_group
    const int warp_m = wid >> 1;
    const int warp_n = wid & 1;
    const int brow = blockIdx.y * 128;
    const int bcol = blockIdx.x * 128;

    // staging coords
    const int ar = tid >> 1;                 // A row 0..127
    const int ac = (tid & 1) * 16;           // A col base
    const int bkr = tid >> 3;                // B k-row 0..31
    const int bnc = (tid & 7) * 16;          // B n base

    float acc[2][8][4] = {};

    for (int k0 = 0; k0 < KK; k0 += 32) {
        __syncthreads();
        // ---- stage A (convert fp32 -> tf32) ----
        {
            int grow = brow + ar;
            const float* ap = &A[(size_t)grow * KK + k0 + ac];
#pragma unroll
            for (int i = 0; i < 4; i++) {
                float4 v = (grow < M) ? *(const float4*)(ap + 4 * i)
                                      : make_float4(0.f, 0.f, 0.f, 0.f);
                uint32_t* dst = &As[ar * PITCH + ac + 4 * i];
                dst[0] = f2tf32(v.x); dst[1] = f2tf32(v.y);
                dst[2] = f2tf32(v.z); dst[3] = f2tf32(v.w);
            }
        }
        // ---- stage B transposed ----
        {
            const float* bp = &B[(size_t)(k0 + bkr) * NN + bcol + bnc];
#pragma unroll
            for (int i = 0; i < 4; i++) {
                float4 v = *(const float4*)(bp + 4 * i);
                Bst[(bnc + 4 * i + 0) * PITCH + bkr] = f2tf32(v.x);
                Bst[(bnc + 4 * i + 1) * PITCH + bkr] = f2tf32(v.y);
                Bst[(bnc + 4 * i + 2) * PITCH + bkr] = f2tf32(v.z);
                Bst[(bnc + 4 * i + 3) * PITCH + bkr] = f2tf32(v.w);
            }
        }
        __syncthreads();

        // ---- compute: 4 k-steps of 8 ----
#pragma unroll
        for (int kt = 0; kt < 4; kt++) {
            uint32_t afr[2][4];
#pragma unroll
            for (int mt = 0; mt < 2; mt++) {
                int r = warp_m * 32 + mt * 16 + lq;
                int kc = kt * 8 + lr;
                afr[mt][0] = As[r * PITCH + kc];
                afr[mt][1] = As[(r + 8) * PITCH + kc];
                afr[mt][2] = As[r * PITCH + kc + 4];
                afr[mt][3] = As[(r + 8) * PITCH + kc + 4];
            }
#pragma unroll
            for (int nt = 0; nt < 8; nt++) {
                int n = warp_n * 64 + nt * 8 + lq;
                int kc = kt * 8 + lr;
                uint32_t b0 = Bst[n * PITCH + kc];
                uint32_t b1 = Bst[n * PITCH + kc + 4];
                mma_tf32(acc[0][nt], afr[0], b0, b1);
                mma_tf32(acc[1][nt], afr[1], b0, b1);
            }
        }
    }

    // ---- C store ----
#pragma unroll
    for (int mt = 0; mt < 2; mt++) {
        int r0 = brow + warp_m * 32 + mt * 16 + lq;
        int r1 = r0 + 8;
#pragma unroll
        for (int nt = 0; nt < 8; nt++) {
            int c = bcol + warp_n * 64 + nt * 8 + lr * 2;
            if (F16OUT) {
                if (r0 < M) {
                    __half2 h = __floats2half2_rn(acc[mt][nt][0], acc[mt][nt][1]);
                    *(__half2*)&Ch[(size_t)r0 * NN + c] = h;
                }
                if (r1 < M) {
                    __half2 h = __floats2half2_rn(acc[mt][nt][2], acc[mt][nt][3]);
                    *(__half2*)&Ch[(size_t)r1 * NN + c] = h;
                }
            } else {
                if (r0 < M)
                    *(float2*)&Cf[(size_t)r0 * NN + c] =
                        make_float2(acc[mt][nt][0], acc[mt][nt][1]);
                if (r1 < M)
                    *(float2*)&Cf[(size_t)r1 * NN + c] =
                        make_float2(acc[mt][nt][2], acc[mt][nt][3]);
            }
        }
    }

    // ---- fused attention scores ----
    float cs[8][2], cd[8][2];
#pragma unroll
    for (int nt = 0; nt < 8; nt++) {
        int c = bcol + warp_n * 64 + nt * 8 + lr * 2;
        cs[nt][0] = va_s[c]; cs[nt][1] = va_s[c + 1];
        cd[nt][0] = va_d[c]; cd[nt][1] = va_d[c + 1];
    }
#pragma unroll
    for (int mt = 0; mt < 2; mt++) {
        float s0 = 0.f, d0 = 0.f, s1 = 0.f, d1 = 0.f;
#pragma unroll
        for (int nt = 0; nt < 8; nt++) {
            s0 = fmaf(acc[mt][nt][0], cs[nt][0], fmaf(acc[mt][nt][1], cs[nt][1], s0));
            d0 = fmaf(acc[mt][nt][0], cd[nt][0], fmaf(acc[mt][nt][1], cd[nt][1], d0));
            s1 = fmaf(acc[mt][nt][2], cs[nt][0], fmaf(acc[mt][nt][3], cs[nt][1], s1));
            d1 = fmaf(acc[mt][nt][2], cd[nt][0], fmaf(acc[mt][nt][3], cd[nt][1], d1));
        }
        // reduce over the 4 lanes of the quad (covers warp's 64 cols)
#pragma unroll
        for (int o = 1; o < 4; o <<= 1) {
            s0 += __shfl_xor_sync(0xffffffffu, s0, o);
            d0 += __shfl_xor_sync(0xffffffffu, d0, o);
            s1 += __shfl_xor_sync(0xffffffffu, s1, o);
            d1 += __shfl_xor_sync(0xffffffffu, d1, o);
        }
        if (lr == 0) {
            int rl0 = warp_m * 32 + mt * 16 + lq;      // local row
            int rl1 = rl0 + 8;
            if (HEADS == 4) {                          // 64-col head == warp width
                int head = blockIdx.x * 2 + warp_n;
                int g0 = brow + rl0, g1 = brow + rl1;
                if (g0 < M) { es[g0 * 4 + head] = s0; ed[g0 * 4 + head] = d0; }
                if (g1 < M) { es[g1 * 4 + head] = s1; ed[g1 * 4 + head] = d1; }
            } else {                                   // single head: smem combine
                sred[0][warp_n][rl0] = s0; sred[1][warp_n][rl0] = d0;
                sred[0][warp_n][rl1] = s1; sred[1][warp_n][rl1] = d1;
            }
        }
    }
    if (HEADS == 1) {
        __syncthreads();
        if (tid < 128) {
            int g = brow + tid;
            if (g < M) {
                es[g] = sred[0][0][tid] + sred[0][1][tid];
                ed[g] = sred[1][0][tid] + sred[1][1][tid];
            }
        }
    }
}

__global__ __launch_bounds__(256) void gemm1_k(const float* __restrict__ x,
                                               const float* __restrict__ W1,
                                               const float* __restrict__ as1,
                                               const float* __restrict__ ad1, int M) {
    gemm_tc_body<256, 128, 4, true>(M, x, W1, nullptr, g_h1h, as1, ad1,
                                    g_es1, g_ed1);
}
__global__ __launch_bounds__(256) void gemm2_k(const float* __restrict__ W2,
                                               const float* __restrict__ as2,
                                               const float* __restrict__ ad2, int M) {
    gemm_tc_body<128, 256, 1, true>(M, g_out1, W2, nullptr, g_h2h, as2, ad2,
                                    g_es2, g_ed2);
}

// ---------------- CSR build ----------------
__global__ void count_k(const int* __restrict__ ei, int E, int Et) {
    int e = blockIdx.x * blockDim.x + threadIdx.x;
    if (e >= Et) return;
    int d = (e < E) ? ei[E + e] : (e - E);
    atomicAdd(&g_cnt[d], 1);
}
__global__ __launch_bounds__(1024) void scan1_k(int N) {
    __shared__ int sh[1024];
    int i = blockIdx.x * 1024 + threadIdx.x;
    int v = (i < N) ? g_cnt[i] : 0;
    sh[threadIdx.x] = v;
    __syncthreads();
#pragma unroll
    for (int off = 1; off < 1024; off <<= 1) {
        int t = (threadIdx.x >= off) ? sh[threadIdx.x - off] : 0;
        __syncthreads();
        sh[threadIdx.x] += t;
        __syncthreads();
    }
    if (i < N) g_scan[i] = sh[threadIdx.x];
    if (threadIdx.x == 1023) g_bsum[blockIdx.x] = sh[1023];
}
__global__ void scan2_k(int nb) {
    __shared__ int sh[64];
    int v = (threadIdx.x < nb) ? g_bsum[threadIdx.x] : 0;
    sh[threadIdx.x] = v;
    __syncthreads();
#pragma unroll
    for (int off = 1; off < 64; off <<= 1) {
        int t = (threadIdx.x >= off) ? sh[threadIdx.x - off] : 0;
        __syncthreads();
        sh[threadIdx.x] += t;
        __syncthreads();
    }
    if (threadIdx.x < nb)
        g_bsum[threadIdx.x] = threadIdx.x ? sh[threadIdx.x - 1] : 0;
}
__global__ void scan3_k(int N, int Et) {
    int i = blockIdx.x * blockDim.x + threadIdx.x;
    if (i >= N) return;
    int c = g_cnt[i];
    g_cnt[i] = 0;  // restore zero-at-entry invariant for the next replay
    int excl = g_scan[i] - c + g_bsum[i >> 10];
    g_rp[i] = excl;
    g_cur[i] = excl;
    if (i == 0) g_rp[N] = Et;
}
__global__ void fill_k(const int* __restrict__ ei, int E, int Et) {
    int e = blockIdx.x * blockDim.x + threadIdx.x;
    if (e >= Et) return;
    int s, d;
    if (e < E) { s = ei[e]; d = ei[E + e]; } else { s = e - E; d = s; }
    int pos = atomicAdd(&g_cur[d], 1);
    g_csr[pos] = s;
}

// ---------------- fused gather aggregation (warp per destination node) --------
// out1[d] = elu( (sum_e p_e * h1[src_e]) / (sum_e p_e) + b1 ), h1 gathered fp16
__device__ __forceinline__ void agg1_edge(int s, float4 ed4, int lane, int h,
                                          float* a, float4& z) {
    float4 es4 = *(const float4*)&g_es1[s * 4];
    float t;
    float4 p;
    t = es4.x + ed4.x; t = t > 0.f ? t : 0.2f * t; p.x = __expf(t);
    t = es4.y + ed4.y; t = t > 0.f ? t : 0.2f * t; p.y = __expf(t);
    t = es4.z + ed4.z; t = t > 0.f ? t : 0.2f * t; p.z = __expf(t);
    t = es4.w + ed4.w; t = t > 0.f ? t : 0.2f * t; p.w = __expf(t);
    z.x += p.x; z.y += p.y; z.z += p.z; z.w += p.w;
    float ph = h == 0 ? p.x : (h == 1 ? p.y : (h == 2 ? p.z : p.w));
    uint4 raw = *(const uint4*)&g_h1h[(size_t)s * 256 + lane * 8];
    uint32_t w0 = raw.x, w1 = raw.y, w2 = raw.z, w3 = raw.w;
    float2 f0 = __half22float2(*reinterpret_cast<__half2*>(&w0));
    float2 f1 = __half22float2(*reinterpret_cast<__half2*>(&w1));
    float2 f2 = __half22float2(*reinterpret_cast<__half2*>(&w2));
    float2 f3 = __half22float2(*reinterpret_cast<__half2*>(&w3));
    a[0] = fmaf(ph, f0.x, a[0]); a[1] = fmaf(ph, f0.y, a[1]);
    a[2] = fmaf(ph, f1.x, a[2]); a[3] = fmaf(ph, f1.y, a[3]);
    a[4] = fmaf(ph, f2.x, a[4]); a[5] = fmaf(ph, f2.y, a[5]);
    a[6] = fmaf(ph, f3.x, a[6]); a[7] = fmaf(ph, f3.y, a[7]);
}

__global__ __launch_bounds__(256) void agg1_k(const float* __restrict__ b1, int N) {
    int d = (blockIdx.x * blockDim.x + threadIdx.x) >> 5;
    int lane = threadIdx.x & 31;
    if (d >= N) return;
    float4 ed4 = *(const float4*)&g_ed1[d * 4];
    int beg = g_rp[d], end = g_rp[d + 1];
    int h = lane >> 3;  // lane covers cols [lane*8, lane*8+8); head = col/64
    float a[8] = {0, 0, 0, 0, 0, 0, 0, 0};
    float4 z = {0, 0, 0, 0};
    int i = beg;
    for (; i + 3 < end; i += 4) {
        int s0 = g_csr[i], s1 = g_csr[i + 1], s2 = g_csr[i + 2], s3 = g_csr[i + 3];
        agg1_edge(s0, ed4, lane, h, a, z);
        agg1_edge(s1, ed4, lane, h, a, z);
        agg1_edge(s2, ed4, lane, h, a, z);
        agg1_edge(s3, ed4, lane, h, a, z);
    }
    for (; i < end; i++) agg1_edge(g_csr[i], ed4, lane, h, a, z);

    float zh = h == 0 ? z.x : (h == 1 ? z.y : (h == 2 ? z.z : z.w));
    float inv = 1.f / zh;
    int col = lane * 8;
    float4 bb0 = *(const float4*)&b1[col];
    float4 bb1 = *(const float4*)&b1[col + 4];
    float4 o0, o1;
    float v;
    v = a[0] * inv + bb0.x; o0.x = v > 0.f ? v : expm1f(v);
    v = a[1] * inv + bb0.y; o0.y = v > 0.f ? v : expm1f(v);
    v = a[2] * inv + bb0.z; o0.z = v > 0.f ? v : expm1f(v);
    v = a[3] * inv + bb0.w; o0.w = v > 0.f ? v : expm1f(v);
    v = a[4] * inv + bb1.x; o1.x = v > 0.f ? v : expm1f(v);
    v = a[5] * inv + bb1.y; o1.y = v > 0.f ? v : expm1f(v);
    v = a[6] * inv + bb1.z; o1.z = v > 0.f ? v : expm1f(v);
    v = a[7] * inv + bb1.w; o1.w = v > 0.f ? v : expm1f(v);
    float* outr = &g_out1[(size_t)d * 256 + col];
    *(float4*)outr = o0;
    *(float4*)(outr + 4) = o1;
}

// out[d] = (sum_e p_e * h2[src_e]) / (sum_e p_e) + b2  (h2 gathered fp16)
__device__ __forceinline__ void agg2_edge(int s, float edv, int lane,
                                          float* a, float& z) {
    float t = g_es2[s] + edv;
    t = t > 0.f ? t : 0.2f * t;
    float p = __expf(t);
    z += p;
    uint2 raw = *(const uint2*)&g_h2h[(size_t)s * 128 + lane * 4];
    uint32_t w0 = raw.x, w1 = raw.y;
    float2 f0 = __half22float2(*reinterpret_cast<__half2*>(&w0));
    float2 f1 = __half22float2(*reinterpret_cast<__half2*>(&w1));
    a[0] = fmaf(p, f0.x, a[0]); a[1] = fmaf(p, f0.y, a[1]);
    a[2] = fmaf(p, f1.x, a[2]); a[3] = fmaf(p, f1.y, a[3]);
}

__global__ __launch_bounds__(256) void agg2_k(float* __restrict__ out,
                                              const float* __restrict__ b2, int N) {
    int d = (blockIdx.x * blockDim.x + threadIdx.x) >> 5;
    int lane = threadIdx.x & 31;
    if (d >= N) return;
    float edv = g_ed2[d];
    int beg = g_rp[d], end = g_rp[d + 1];
    float a[4] = {0, 0, 0, 0};
    float z = 0.f;
    int i = beg;
    for (; i + 3 < end; i += 4) {
        int s0 = g_csr[i], s1 = g_csr[i + 1], s2 = g_csr[i + 2], s3 = g_csr[i + 3];
        agg2_edge(s0, edv, lane, a, z);
        agg2_edge(s1, edv, lane, a, z);
        agg2_edge(s2, edv, lane, a, z);
        agg2_edge(s3, edv, lane, a, z);
    }
    for (; i < end; i++) agg2_edge(g_csr[i], edv, lane, a, z);

    float inv = 1.f / z;
    int col = lane * 4;
    float4 bb = *(const float4*)&b2[col];
    float4 o;
    o.x = a[0] * inv + bb.x; o.y = a[1] * inv + bb.y;
    o.z = a[2] * inv + bb.z; o.w = a[3] * inv + bb.w;
    *(float4*)&out[(size_t)d * 128 + col] = o;
}

// ---------------- launch ----------------
extern "C" void kernel_launch(void* const* d_in, const int* in_sizes, int n_in,
                              void* d_out, int out_size) {
    const float* x   = (const float*)d_in[0];
    const int*   ei  = (const int*)d_in[1];
    const float* W1  = (const float*)d_in[2];
    const float* as1 = (const float*)d_in[3];
    const float* ad1 = (const float*)d_in[4];
    const float* b1  = (const float*)d_in[5];
    const float* W2  = (const float*)d_in[6];
    const float* as2 = (const float*)d_in[7];
    const float* ad2 = (const float*)d_in[8];
    const float* b2  = (const float*)d_in[9];
    float* out = (float*)d_out;

    int N  = in_sizes[0] / 128;  // in_dim = 128
    int E  = in_sizes[1] / 2;
    int Et = E + N;
    int nb = (N + 1023) / 1024;
    int gy = (N + 127) / 128;

    // lazily-created side stream + fork/join events (created on the
    // correctness call, which precedes graph capture)
    static cudaStream_t s1 = nullptr;
    static cudaEvent_t ev0 = nullptr, ev1 = nullptr;
    if (!s1) {
        cudaStreamCreateWithFlags(&s1, cudaStreamNonBlocking);
        cudaEventCreateWithFlags(&ev0, cudaEventDisableTiming);
        cudaEventCreateWithFlags(&ev1, cudaEventDisableTiming);
    }

    // ---- fork: CSR build on s1, overlapped with gemm1 on the main stream ----
    // Invariant: g_cnt == 0 at entry (static init on first call; scan3_k
    // re-zeroes it inline). Side stream fully joins at ev1.
    cudaEventRecord(ev0, 0);
    cudaStreamWaitEvent(s1, ev0, 0);
    count_k<<<(Et + 255) / 256, 256, 0, s1>>>(ei, E, Et);
    scan1_k<<<nb, 1024, 0, s1>>>(N);
    scan2_k<<<1, 64, 0, s1>>>(nb);
    scan3_k<<<(N + 255) / 256, 256, 0, s1>>>(N, Et);
    fill_k<<<(Et + 255) / 256, 256, 0, s1>>>(ei, E, Et);
    cudaEventRecord(ev1, s1);

    // ---- Layer 1 (main stream) ----
    gemm1_k<<<dim3(2, gy), 256>>>(x, W1, as1, ad1, N);
    cudaStreamWaitEvent(0, ev1, 0);  // join CSR before aggregation
    agg1_k<<<(N * 32 + 255) / 256, 256>>>(b1, N);

    // ---- Layer 2 ----
    gemm2_k<<<dim3(1, gy), 256>>>(W2, as2, ad2, N);
    agg2_k<<<(N * 32 + 255) / 256, 256>>>(out, b2, N);
}

// round 13
// speedup vs baseline: 2.6987x; 1.0201x over previous
#include <cuda_runtime.h>
#include <cuda_fp16.h>
#include <cstdint>
#include <math.h>

// Problem-shape constants (from reference setup_inputs)
#define NMAX 50000
#define EMAX 800000
#define ETMAX (EMAX + NMAX)

// ---------------- device scratch (no allocations allowed) ----------------
__device__ __align__(16) __half g_h1h[NMAX * 256];  // x@W1 as fp16 (gather src)
__device__ __align__(16) float g_out1[NMAX * 256];  // layer1 out (post-ELU)
__device__ __align__(16) __half g_h2h[NMAX * 128];  // out1@W2 as fp16 (gather src)
__device__ __align__(16) float g_es1[NMAX * 4];
__device__ __align__(16) float g_ed1[NMAX * 4];
__device__ __align__(16) float g_es2[NMAX];
__device__ __align__(16) float g_ed2[NMAX];

// CSR-by-destination (built once per launch, reused by both layers)
__device__ int g_cnt[NMAX];   // invariant: zero at launch entry (static init;
                              // scan3_k re-zeroes it after reading)
__device__ int g_scan[NMAX];
__device__ int g_bsum[64];
__device__ int g_rp[NMAX + 1];
__device__ int g_cur[NMAX];
__device__ int g_csr[ETMAX];

// ---------------- tf32 tensor-core helpers ----------------
__device__ __forceinline__ uint32_t f2tf32(float f) {
    uint32_t r;
    asm("cvt.rna.tf32.f32 %0, %1;" : "=r"(r) : "f"(f));
    return r;
}
__device__ __forceinline__ void mma_tf32(float* c, const uint32_t* a,
                                         uint32_t b0, uint32_t b1) {
    asm volatile(
        "mma.sync.aligned.m16n8k8.row.col.f32.tf32.tf32.f32 "
        "{%0,%1,%2,%3}, {%4,%5,%6,%7}, {%8,%9}, {%0,%1,%2,%3};"
        : "+f"(c[0]), "+f"(c[1]), "+f"(c[2]), "+f"(c[3])
        : "r"(a[0]), "r"(a[1]), "r"(a[2]), "r"(a[3]), "r"(b0), "r"(b1));
}

// ---------------- tf32 tensor-core GEMM + fused score epilogue ----------------
// C[M,NN] = A[M,KK] @ B[KK,NN]. Block 128x128, BK=32, 8 warps (4m x 2n),
// each warp 32x64 = 2(m) x 8(n) m16n8k8 tiles. Pitch-36 smem (conflict-free).
// Epilogue computes es/ed = C . a_src/a_dst from exact fp32 accumulators.
#define PITCH 36
template <int NN, int KK, int HEADS, bool F16OUT>
__device__ __forceinline__ void gemm_tc_body(
    int M, const float* __restrict__ A, const float* __restrict__ B,
    float* __restrict__ Cf, __half* __restrict__ Ch,
    const float* __restrict__ va_s, const float* __restrict__ va_d,
    float* __restrict__ es, float* __restrict__ ed) {
    __shared__ uint32_t As[128 * PITCH];
    __shared__ uint32_t Bst[128 * PITCH];      // transposed: [n][k]
    __shared__ float sred[2][2][128];          // [s/d][warp_n][row] (HEADS==1)

    const int tid = threadIdx.x;
    const int wid = tid >> 5;
    const int lane = tid & 31;
    const int lq = lane >> 2;   // groupID
    const int lr = lane & 3;    // threadID_in_group
    const int warp_m = wid >> 1;
    const int warp_n = wid & 1;
    const int brow = blockIdx.y * 128;
    const int bcol = blockIdx.x * 128;

    // staging coords
    const int ar = tid >> 1;                 // A row 0..127
    const int ac = (tid & 1) * 16;           // A col base
    const int bkr = tid >> 3;                // B k-row 0..31
    const int bnc = (tid & 7) * 16;          // B n base

    float acc[2][8][4] = {};

    for (int k0 = 0; k0 < KK; k0 += 32) {
        __syncthreads();
        // ---- stage A (convert fp32 -> tf32) ----
        {
            int grow = brow + ar;
            const float* ap = &A[(size_t)grow * KK + k0 + ac];
#pragma unroll
            for (int i = 0; i < 4; i++) {
                float4 v = (grow < M) ? *(const float4*)(ap + 4 * i)
                                      : make_float4(0.f, 0.f, 0.f, 0.f);
                uint32_t* dst = &As[ar * PITCH + ac + 4 * i];
                dst[0] = f2tf32(v.x); dst[1] = f2tf32(v.y);
                dst[2] = f2tf32(v.z); dst[3] = f2tf32(v.w);
            }
        }
        // ---- stage B transposed ----
        {
            const float* bp = &B[(size_t)(k0 + bkr) * NN + bcol + bnc];
#pragma unroll
            for (int i = 0; i < 4; i++) {
                float4 v = *(const float4*)(bp + 4 * i);
                Bst[(bnc + 4 * i + 0) * PITCH + bkr] = f2tf32(v.x);
                Bst[(bnc + 4 * i + 1) * PITCH + bkr] = f2tf32(v.y);
                Bst[(bnc + 4 * i + 2) * PITCH + bkr] = f2tf32(v.z);
                Bst[(bnc + 4 * i + 3) * PITCH + bkr] = f2tf32(v.w);
            }
        }
        __syncthreads();

        // ---- compute: 4 k-steps of 8 ----
#pragma unroll
        for (int kt = 0; kt < 4; kt++) {
            uint32_t afr[2][4];
#pragma unroll
            for (int mt = 0; mt < 2; mt++) {
                int r = warp_m * 32 + mt * 16 + lq;
                int kc = kt * 8 + lr;
                afr[mt][0] = As[r * PITCH + kc];
                afr[mt][1] = As[(r + 8) * PITCH + kc];
                afr[mt][2] = As[r * PITCH + kc + 4];
                afr[mt][3] = As[(r + 8) * PITCH + kc + 4];
            }
#pragma unroll
            for (int nt = 0; nt < 8; nt++) {
                int n = warp_n * 64 + nt * 8 + lq;
                int kc = kt * 8 + lr;
                uint32_t b0 = Bst[n * PITCH + kc];
                uint32_t b1 = Bst[n * PITCH + kc + 4];
                mma_tf32(acc[0][nt], afr[0], b0, b1);
                mma_tf32(acc[1][nt], afr[1], b0, b1);
            }
        }
    }

    // ---- C store ----
#pragma unroll
    for (int mt = 0; mt < 2; mt++) {
        int r0 = brow + warp_m * 32 + mt * 16 + lq;
        int r1 = r0 + 8;
#pragma unroll
        for (int nt = 0; nt < 8; nt++) {
            int c = bcol + warp_n * 64 + nt * 8 + lr * 2;
            if (F16OUT) {
                if (r0 < M) {
                    __half2 h = __floats2half2_rn(acc[mt][nt][0], acc[mt][nt][1]);
                    *(__half2*)&Ch[(size_t)r0 * NN + c] = h;
                }
                if (r1 < M) {
                    __half2 h = __floats2half2_rn(acc[mt][nt][2], acc[mt][nt][3]);
                    *(__half2*)&Ch[(size_t)r1 * NN + c] = h;
                }
            } else {
                if (r0 < M)
                    *(float2*)&Cf[(size_t)r0 * NN + c] =
                        make_float2(acc[mt][nt][0], acc[mt][nt][1]);
                if (r1 < M)
                    *(float2*)&Cf[(size_t)r1 * NN + c] =
                        make_float2(acc[mt][nt][2], acc[mt][nt][3]);
            }
        }
    }

    // ---- fused attention scores ----
    float cs[8][2], cd[8][2];
#pragma unroll
    for (int nt = 0; nt < 8; nt++) {
        int c = bcol + warp_n * 64 + nt * 8 + lr * 2;
        cs[nt][0] = va_s[c]; cs[nt][1] = va_s[c + 1];
        cd[nt][0] = va_d[c]; cd[nt][1] = va_d[c + 1];
    }
#pragma unroll
    for (int mt = 0; mt < 2; mt++) {
        float s0 = 0.f, d0 = 0.f, s1 = 0.f, d1 = 0.f;
#pragma unroll
        for (int nt = 0; nt < 8; nt++) {
            s0 = fmaf(acc[mt][nt][0], cs[nt][0], fmaf(acc[mt][nt][1], cs[nt][1], s0));
            d0 = fmaf(acc[mt][nt][0], cd[nt][0], fmaf(acc[mt][nt][1], cd[nt][1], d0));
            s1 = fmaf(acc[mt][nt][2], cs[nt][0], fmaf(acc[mt][nt][3], cs[nt][1], s1));
            d1 = fmaf(acc[mt][nt][2], cd[nt][0], fmaf(acc[mt][nt][3], cd[nt][1], d1));
        }
        // reduce over the 4 lanes of the quad (covers warp's 64 cols)
#pragma unroll
        for (int o = 1; o < 4; o <<= 1) {
            s0 += __shfl_xor_sync(0xffffffffu, s0, o);
            d0 += __shfl_xor_sync(0xffffffffu, d0, o);
            s1 += __shfl_xor_sync(0xffffffffu, s1, o);
            d1 += __shfl_xor_sync(0xffffffffu, d1, o);
        }
        if (lr == 0) {
            int rl0 = warp_m * 32 + mt * 16 + lq;      // local row
            int rl1 = rl0 + 8;
            if (HEADS == 4) {                          // 64-col head == warp width
                int head = blockIdx.x * 2 + warp_n;
                int g0 = brow + rl0, g1 = brow + rl1;
                if (g0 < M) { es[g0 * 4 + head] = s0; ed[g0 * 4 + head] = d0; }
                if (g1 < M) { es[g1 * 4 + head] = s1; ed[g1 * 4 + head] = d1; }
            } else {                                   // single head: smem combine
                sred[0][warp_n][rl0] = s0; sred[1][warp_n][rl0] = d0;
                sred[0][warp_n][rl1] = s1; sred[1][warp_n][rl1] = d1;
            }
        }
    }
    if (HEADS == 1) {
        __syncthreads();
        if (tid < 128) {
            int g = brow + tid;
            if (g < M) {
                es[g] = sred[0][0][tid] + sred[0][1][tid];
                ed[g] = sred[1][0][tid] + sred[1][1][tid];
            }
        }
    }
}

__global__ __launch_bounds__(256) void gemm1_k(const float* __restrict__ x,
                                               const float* __restrict__ W1,
                                               const float* __restrict__ as1,
                                               const float* __restrict__ ad1, int M) {
    gemm_tc_body<256, 128, 4, true>(M, x, W1, nullptr, g_h1h, as1, ad1,
                                    g_es1, g_ed1);
}
__global__ __launch_bounds__(256) void gemm2_k(const float* __restrict__ W2,
                                               const float* __restrict__ as2,
                                               const float* __restrict__ ad2, int M) {
    gemm_tc_body<128, 256, 1, true>(M, g_out1, W2, nullptr, g_h2h, as2, ad2,
                                    g_es2, g_ed2);
}

// ---------------- CSR build ----------------
__global__ void count_k(const int* __restrict__ ei, int E, int Et) {
    int e = blockIdx.x * blockDim.x + threadIdx.x;
    if (e >= Et) return;
    int d = (e < E) ? ei[E + e] : (e - E);
    atomicAdd(&g_cnt[d], 1);
}
__global__ __launch_bounds__(1024) void scan1_k(int N) {
    __shared__ int sh[1024];
    int i = blockIdx.x * 1024 + threadIdx.x;
    int v = (i < N) ? g_cnt[i] : 0;
    sh[threadIdx.x] = v;
    __syncthreads();
#pragma unroll
    for (int off = 1; off < 1024; off <<= 1) {
        int t = (threadIdx.x >= off) ? sh[threadIdx.x - off] : 0;
        __syncthreads();
        sh[threadIdx.x] += t;
        __syncthreads();
    }
    if (i < N) g_scan[i] = sh[threadIdx.x];
    if (threadIdx.x == 1023) g_bsum[blockIdx.x] = sh[1023];
}
__global__ void scan2_k(int nb) {
    __shared__ int sh[64];
    int v = (threadIdx.x < nb) ? g_bsum[threadIdx.x] : 0;
    sh[threadIdx.x] = v;
    __syncthreads();
#pragma unroll
    for (int off = 1; off < 64; off <<= 1) {
        int t = (threadIdx.x >= off) ? sh[threadIdx.x - off] : 0;
        __syncthreads();
        sh[threadIdx.x] += t;
        __syncthreads();
    }
    if (threadIdx.x < nb)
        g_bsum[threadIdx.x] = threadIdx.x ? sh[threadIdx.x - 1] : 0;
}
__global__ void scan3_k(int N, int Et) {
    int i = blockIdx.x * blockDim.x + threadIdx.x;
    if (i >= N) return;
    int c = g_cnt[i];
    g_cnt[i] = 0;  // restore zero-at-entry invariant for the next replay
    int excl = g_scan[i] - c + g_bsum[i >> 10];
    g_rp[i] = excl;
    g_cur[i] = excl;
    if (i == 0) g_rp[N] = Et;
}
__global__ void fill_k(const int* __restrict__ ei, int E, int Et) {
    int e = blockIdx.x * blockDim.x + threadIdx.x;
    if (e >= Et) return;
    int s, d;
    if (e < E) { s = ei[e]; d = ei[E + e]; } else { s = e - E; d = s; }
    int pos = atomicAdd(&g_cur[d], 1);
    g_csr[pos] = s;
}

// ---------------- fused gather aggregation (2 warps per destination) ---------
// agg1: warp covers 128 of 256 cols (lane: 4 cols, 8B fp16). Heads split
// cleanly across warps (cols disjoint), each lane computes only ITS head's exp.
__device__ __forceinline__ void agg1_edge(int s, float edh, int col, int h,
                                          float& a0, float& a1, float& a2,
                                          float& a3, float& z) {
    float t = g_es1[s * 4 + h] + edh;
    t = t > 0.f ? t : 0.2f * t;
    float p = __expf(t);
    z += p;
    uint2 raw = *(const uint2*)&g_h1h[(size_t)s * 256 + col];
    uint32_t w0 = raw.x, w1 = raw.y;
    float2 f0 = __half22float2(*reinterpret_cast<__half2*>(&w0));
    float2 f1 = __half22float2(*reinterpret_cast<__half2*>(&w1));
    a0 = fmaf(p, f0.x, a0); a1 = fmaf(p, f0.y, a1);
    a2 = fmaf(p, f1.x, a2); a3 = fmaf(p, f1.y, a3);
}

__global__ __launch_bounds__(256) void agg1_k(const float* __restrict__ b1, int N) {
    int gw = (blockIdx.x * blockDim.x + threadIdx.x) >> 5;
    int d = gw >> 1;          // destination node
    int wh = gw & 1;          // which half of the feature row
    int lane = threadIdx.x & 31;
    if (d >= N) return;
    int col = wh * 128 + lane * 4;
    int h = col >> 6;         // this lane's head
    float edh = g_ed1[d * 4 + h];
    int beg = g_rp[d], end = g_rp[d + 1];
    float a0 = 0.f, a1 = 0.f, a2 = 0.f, a3 = 0.f, z = 0.f;
    int i = beg;
    for (; i + 3 < end; i += 4) {
        int s0 = g_csr[i], s1 = g_csr[i + 1], s2 = g_csr[i + 2], s3 = g_csr[i + 3];
        agg1_edge(s0, edh, col, h, a0, a1, a2, a3, z);
        agg1_edge(s1, edh, col, h, a0, a1, a2, a3, z);
        agg1_edge(s2, edh, col, h, a0, a1, a2, a3, z);
        agg1_edge(s3, edh, col, h, a0, a1, a2, a3, z);
    }
    for (; i < end; i++) agg1_edge(g_csr[i], edh, col, h, a0, a1, a2, a3, z);

    float inv = 1.f / z;
    float4 bb = *(const float4*)&b1[col];
    float4 o;
    float v;
    v = a0 * inv + bb.x; o.x = v > 0.f ? v : expm1f(v);
    v = a1 * inv + bb.y; o.y = v > 0.f ? v : expm1f(v);
    v = a2 * inv + bb.z; o.z = v > 0.f ? v : expm1f(v);
    v = a3 * inv + bb.w; o.w = v > 0.f ? v : expm1f(v);
    // streaming store: keep the fp16 gather tables L2-resident
    __stcs((float4*)&g_out1[(size_t)d * 256 + col], o);
}

// agg2: warp covers 64 of 128 cols (lane: 2 cols, 4B fp16)
__device__ __forceinline__ void agg2_edge(int s, float edv, int col,
                                          float& a0, float& a1, float& z) {
    float t = g_es2[s] + edv;
    t = t > 0.f ? t : 0.2f * t;
    float p = __expf(t);
    z += p;
    uint32_t w = *(const uint32_t*)&g_h2h[(size_t)s * 128 + col];
    float2 f = __half22float2(*reinterpret_cast<__half2*>(&w));
    a0 = fmaf(p, f.x, a0); a1 = fmaf(p, f.y, a1);
}

__global__ __launch_bounds__(256) void agg2_k(float* __restrict__ out,
                                              const float* __restrict__ b2, int N) {
    int gw = (blockIdx.x * blockDim.x + threadIdx.x) >> 5;
    int d = gw >> 1;
    int wh = gw & 1;
    int lane = threadIdx.x & 31;
    if (d >= N) return;
    int col = wh * 64 + lane * 2;
    float edv = g_ed2[d];
    int beg = g_rp[d], end = g_rp[d + 1];
    float a0 = 0.f, a1 = 0.f, z = 0.f;
    int i = beg;
    for (; i + 3 < end; i += 4) {
        int s0 = g_csr[i], s1 = g_csr[i + 1], s2 = g_csr[i + 2], s3 = g_csr[i + 3];
        agg2_edge(s0, edv, col, a0, a1, z);
        agg2_edge(s1, edv, col, a0, a1, z);
        agg2_edge(s2, edv, col, a0, a1, z);
        agg2_edge(s3, edv, col, a0, a1, z);
    }
    for (; i < end; i++) agg2_edge(g_csr[i], edv, col, a0, a1, z);

    float inv = 1.f / z;
    float2 o;
    o.x = a0 * inv + b2[col];
    o.y = a1 * inv + b2[col + 1];
    __stcs((float2*)&out[(size_t)d * 128 + col], o);
}

// ---------------- launch ----------------
extern "C" void kernel_launch(void* const* d_in, const int* in_sizes, int n_in,
                              void* d_out, int out_size) {
    const float* x   = (const float*)d_in[0];
    const int*   ei  = (const int*)d_in[1];
    const float* W1  = (const float*)d_in[2];
    const float* as1 = (const float*)d_in[3];
    const float* ad1 = (const float*)d_in[4];
    const float* b1  = (const float*)d_in[5];
    const float* W2  = (const float*)d_in[6];
    const float* as2 = (const float*)d_in[7];
    const float* ad2 = (const float*)d_in[8];
    const float* b2  = (const float*)d_in[9];
    float* out = (float*)d_out;

    int N  = in_sizes[0] / 128;  // in_dim = 128
    int E  = in_sizes[1] / 2;
    int Et = E + N;
    int nb = (N + 1023) / 1024;
    int gy = (N + 127) / 128;

    // lazily-created side stream + fork/join events (created on the
    // correctness call, which precedes graph capture)
    static cudaStream_t s1 = nullptr;
    static cudaEvent_t ev0 = nullptr, ev1 = nullptr;
    if (!s1) {
        cudaStreamCreateWithFlags(&s1, cudaStreamNonBlocking);
        cudaEventCreateWithFlags(&ev0, cudaEventDisableTiming);
        cudaEventCreateWithFlags(&ev1, cudaEventDisableTiming);
    }

    // ---- fork: CSR build on s1, overlapped with gemm1 on the main stream ----
    // Invariant: g_cnt == 0 at entry (static init on first call; scan3_k
    // re-zeroes it inline). Side stream fully joins at ev1.
    cudaEventRecord(ev0, 0);
    cudaStreamWaitEvent(s1, ev0, 0);
    count_k<<<(Et + 255) / 256, 256, 0, s1>>>(ei, E, Et);
    scan1_k<<<nb, 1024, 0, s1>>>(N);
    scan2_k<<<1, 64, 0, s1>>>(nb);
    scan3_k<<<(N + 255) / 256, 256, 0, s1>>>(N, Et);
    fill_k<<<(Et + 255) / 256, 256, 0, s1>>>(ei, E, Et);
    cudaEventRecord(ev1, s1);

    // ---- Layer 1 (main stream) ----
    gemm1_k<<<dim3(2, gy), 256>>>(x, W1, as1, ad1, N);
    cudaStreamWaitEvent(0, ev1, 0);  // join CSR before aggregation
    agg1_k<<<(N * 64 + 255) / 256, 256>>>(b1, N);

    // ---- Layer 2 ----
    gemm2_k<<<dim3(1, gy), 256>>>(W2, as2, ad2, N);
    agg2_k<<<(N * 64 + 255) / 256, 256>>>(out, b2, N);
}